// round 2
// baseline (speedup 1.0000x reference)
#include <cuda_runtime.h>
#include <cuda_bf16.h>
#include <math.h>

#define BB 2
#define LL 2048
#define DD 1024
#define HH 16
#define HDIM 64
#define D3 3072
#define RLEN 4095   // 2*L - 1

// Scratch (no allocation allowed): 48MB proj buffer + bias table
__device__ float g_proj[(size_t)BB * LL * D3];
__device__ float g_scores[HH * RLEN];

// ---------------------------------------------------------------------------
// Kernel 1: TISA bias table. scores[h][r] = sum_k amp*exp(-|sharp|*(off-rel)^2)
// ---------------------------------------------------------------------------
__global__ __launch_bounds__(256) void scores_kernel(const float* __restrict__ off,
                                                     const float* __restrict__ amp,
                                                     const float* __restrict__ shp)
{
    int h = blockIdx.x;
    __shared__ float so[16], sa[16], ss[16];
    if (threadIdx.x < 16) {
        so[threadIdx.x] = off[h * 16 + threadIdx.x];
        sa[threadIdx.x] = amp[h * 16 + threadIdx.x];
        ss[threadIdx.x] = fabsf(shp[h * 16 + threadIdx.x]);
    }
    __syncthreads();
    for (int r = threadIdx.x; r < RLEN; r += blockDim.x) {
        float rel = (float)(r - (LL - 1));
        float acc = 0.f;
#pragma unroll
        for (int k = 0; k < 16; k++) {
            float d = so[k] - rel;
            acc += sa[k] * expf(-ss[k] * d * d);
        }
        g_scores[h * RLEN + r] = acc;
    }
}

// ---------------------------------------------------------------------------
// Kernel 2: proj[m][n] = sum_k x[m][k] * w_in[n][k]   (NT sgemm)
// M=4096, N=3072, K=1024. 128x128 block, BK=8, 8x8 per thread, 256 threads.
// ---------------------------------------------------------------------------
__global__ __launch_bounds__(256) void sgemm_nt(const float* __restrict__ A,
                                                const float* __restrict__ W)
{
    const int K = DD;
    const int N = D3;
    __shared__ float As[8 * 128];
    __shared__ float Ws[8 * 128];

    int tid = threadIdx.x;
    int tx = tid & 15, ty = tid >> 4;
    int bm = blockIdx.y * 128, bn = blockIdx.x * 128;

    int lrow = tid >> 1;        // 0..127
    int lk   = (tid & 1) << 2;  // 0 or 4

    const float* Ap = A + (size_t)(bm + lrow) * K + lk;
    const float* Wp = W + (size_t)(bn + lrow) * K + lk;

    float4 a = *(const float4*)Ap;
    float4 w = *(const float4*)Wp;

    float acc[8][8];
#pragma unroll
    for (int i = 0; i < 8; i++)
#pragma unroll
        for (int j = 0; j < 8; j++) acc[i][j] = 0.f;

    for (int k0 = 0; k0 < K; k0 += 8) {
        As[(lk + 0) * 128 + lrow] = a.x;
        As[(lk + 1) * 128 + lrow] = a.y;
        As[(lk + 2) * 128 + lrow] = a.z;
        As[(lk + 3) * 128 + lrow] = a.w;
        Ws[(lk + 0) * 128 + lrow] = w.x;
        Ws[(lk + 1) * 128 + lrow] = w.y;
        Ws[(lk + 2) * 128 + lrow] = w.z;
        Ws[(lk + 3) * 128 + lrow] = w.w;
        __syncthreads();

        if (k0 + 8 < K) {  // prefetch next K-slab while computing
            a = *(const float4*)(Ap + k0 + 8);
            w = *(const float4*)(Wp + k0 + 8);
        }

#pragma unroll
        for (int kk = 0; kk < 8; kk++) {
            float4 a0 = *(const float4*)(&As[kk * 128 + ty * 4]);
            float4 a1 = *(const float4*)(&As[kk * 128 + 64 + ty * 4]);
            float4 w0 = *(const float4*)(&Ws[kk * 128 + tx * 4]);
            float4 w1 = *(const float4*)(&Ws[kk * 128 + 64 + tx * 4]);
            float rm[8] = {a0.x, a0.y, a0.z, a0.w, a1.x, a1.y, a1.z, a1.w};
            float rn[8] = {w0.x, w0.y, w0.z, w0.w, w1.x, w1.y, w1.z, w1.w};
#pragma unroll
            for (int i = 0; i < 8; i++)
#pragma unroll
                for (int j = 0; j < 8; j++)
                    acc[i][j] = fmaf(rm[i], rn[j], acc[i][j]);
        }
        __syncthreads();
    }

#pragma unroll
    for (int i = 0; i < 8; i++) {
        int r = bm + ((i < 4) ? (ty * 4 + i) : (64 + ty * 4 + i - 4));
        float4 c0 = make_float4(acc[i][0], acc[i][1], acc[i][2], acc[i][3]);
        float4 c1 = make_float4(acc[i][4], acc[i][5], acc[i][6], acc[i][7]);
        *(float4*)(g_proj + (size_t)r * N + bn + tx * 4) = c0;
        *(float4*)(g_proj + (size_t)r * N + bn + 64 + tx * 4) = c1;
    }
}

// ---------------------------------------------------------------------------
// Kernel 3: flash attention with TISA bias.
// Block = (b, h, 64-query tile), 256 threads (16x16), KV tiles of 64.
// Thread (ty,tx): S rows {ty+16i}, S cols {tx+16j}; O rows {ty+16i}, O cols {tx*4+j}.
// proj row layout: [k(0..1023) | v(1024..2047) | q(2048..3071)]
// ---------------------------------------------------------------------------
__global__ __launch_bounds__(256) void attn_kernel(float* __restrict__ out)
{
    extern __shared__ float sm[];
    float* Qs = sm;               // [64][64]
    float* Ks = Qs + 64 * 64;     // [64][68] padded
    float* Vs = Ks + 64 * 68;     // [64][64]
    float* Ps = Vs + 64 * 64;     // [64][65] padded
    float* sb = Ps + 64 * 65;     // [128] bias diagonal slice

    const int qb = blockIdx.x * 64;
    const int h  = blockIdx.y;
    const int b  = blockIdx.z;
    const int tid = threadIdx.x;
    const int tx = tid & 15, ty = tid >> 4;

    const float* base = g_proj + (size_t)b * LL * D3;
    const float* kptr = base + h * HDIM;              // k at offset 0
    const float* vptr = base + DD + h * HDIM;         // v at offset D
    const float* qptr = base + 2 * DD + h * HDIM;     // q at offset 2D
    const float* srow = g_scores + h * RLEN;
    const float scale = 0.125f;  // 1/sqrt(64)

    // Load Q tile (row-major, stride 64)
    for (int i = tid; i < 1024; i += 256) {
        int r = i >> 4;
        int d = (i & 15) << 2;
        float4 v = *(const float4*)(qptr + (size_t)(qb + r) * D3 + d);
        *(float4*)(Qs + r * 64 + d) = v;
    }

    float m_run[4], l_run[4], O[4][4];
#pragma unroll
    for (int i = 0; i < 4; i++) {
        m_run[i] = -3.0e38f; l_run[i] = 0.f;
#pragma unroll
        for (int j = 0; j < 4; j++) O[i][j] = 0.f;
    }

    for (int kb = 0; kb < LL; kb += 64) {
        __syncthreads();
        // Load K (stride 68), V (stride 64), bias slice
        for (int i = tid; i < 1024; i += 256) {
            int r = i >> 4;
            int d = (i & 15) << 2;
            float4 kv = *(const float4*)(kptr + (size_t)(kb + r) * D3 + d);
            Ks[r * 68 + d + 0] = kv.x;
            Ks[r * 68 + d + 1] = kv.y;
            Ks[r * 68 + d + 2] = kv.z;
            Ks[r * 68 + d + 3] = kv.w;
            float4 vv = *(const float4*)(vptr + (size_t)(kb + r) * D3 + d);
            *(float4*)(Vs + r * 64 + d) = vv;
        }
        if (tid < 127) sb[tid] = srow[qb - kb + 2047 - 63 + tid];
        __syncthreads();

        // S = Q K^T
        float S[4][4];
#pragma unroll
        for (int i = 0; i < 4; i++)
#pragma unroll
            for (int j = 0; j < 4; j++) S[i][j] = 0.f;

#pragma unroll
        for (int d4 = 0; d4 < 16; d4++) {
            float4 rq[4], rk[4];
#pragma unroll
            for (int i = 0; i < 4; i++)
                rq[i] = *(const float4*)(Qs + (ty + 16 * i) * 64 + d4 * 4);
#pragma unroll
            for (int j = 0; j < 4; j++)
                rk[j] = *(const float4*)(Ks + (tx + 16 * j) * 68 + d4 * 4);
#pragma unroll
            for (int i = 0; i < 4; i++)
#pragma unroll
                for (int j = 0; j < 4; j++) {
                    S[i][j] = fmaf(rq[i].x, rk[j].x, S[i][j]);
                    S[i][j] = fmaf(rq[i].y, rk[j].y, S[i][j]);
                    S[i][j] = fmaf(rq[i].z, rk[j].z, S[i][j]);
                    S[i][j] = fmaf(rq[i].w, rk[j].w, S[i][j]);
                }
        }

        // Online softmax (rows reduced over 16 tx lanes)
#pragma unroll
        for (int i = 0; i < 4; i++) {
            float mx = -3.0e38f;
#pragma unroll
            for (int j = 0; j < 4; j++) {
                S[i][j] = S[i][j] * scale + sb[(ty + 16 * i) - (tx + 16 * j) + 63];
                mx = fmaxf(mx, S[i][j]);
            }
#pragma unroll
            for (int s = 8; s > 0; s >>= 1)
                mx = fmaxf(mx, __shfl_xor_sync(0xffffffffu, mx, s, 16));
            float mnew = fmaxf(m_run[i], mx);
            float corr = __expf(m_run[i] - mnew);
            m_run[i] = mnew;
            float rs = 0.f;
#pragma unroll
            for (int j = 0; j < 4; j++) {
                float p = __expf(S[i][j] - mnew);
                Ps[(ty + 16 * i) * 65 + (tx + 16 * j)] = p;
                rs += p;
            }
#pragma unroll
            for (int s = 8; s > 0; s >>= 1)
                rs += __shfl_xor_sync(0xffffffffu, rs, s, 16);
            l_run[i] = l_run[i] * corr + rs;
#pragma unroll
            for (int j = 0; j < 4; j++) O[i][j] *= corr;
        }
        __syncthreads();

        // O += P V
#pragma unroll 8
        for (int kv = 0; kv < 64; kv++) {
            float pv[4];
#pragma unroll
            for (int i = 0; i < 4; i++) pv[i] = Ps[(ty + 16 * i) * 65 + kv];
            float4 vv = *(const float4*)(Vs + kv * 64 + tx * 4);
#pragma unroll
            for (int i = 0; i < 4; i++) {
                O[i][0] = fmaf(pv[i], vv.x, O[i][0]);
                O[i][1] = fmaf(pv[i], vv.y, O[i][1]);
                O[i][2] = fmaf(pv[i], vv.z, O[i][2]);
                O[i][3] = fmaf(pv[i], vv.w, O[i][3]);
            }
        }
    }

    // Normalize and write out[b, l, h*64 + d]
#pragma unroll
    for (int i = 0; i < 4; i++) {
        float inv = 1.0f / l_run[i];
        float4 o = make_float4(O[i][0] * inv, O[i][1] * inv, O[i][2] * inv, O[i][3] * inv);
        size_t row = (size_t)(b * LL + qb + ty + 16 * i);
        *(float4*)(out + row * DD + h * HDIM + tx * 4) = o;
    }
}

// ---------------------------------------------------------------------------
extern "C" void kernel_launch(void* const* d_in, const int* in_sizes, int n_in,
                              void* d_out, int out_size)
{
    const float* x    = (const float*)d_in[0];
    const float* w_in = (const float*)d_in[1];
    const float* off  = (const float*)d_in[2];
    const float* amp  = (const float*)d_in[3];
    const float* shp  = (const float*)d_in[4];
    float* out = (float*)d_out;

    scores_kernel<<<HH, 256>>>(off, amp, shp);

    dim3 ggrid(D3 / 128, (BB * LL) / 128);
    sgemm_nt<<<ggrid, 256>>>(x, w_in);

    const int smem_bytes = (64 * 64 + 64 * 68 + 64 * 64 + 64 * 65 + 128) * 4;  // 67328
    cudaFuncSetAttribute(attn_kernel, cudaFuncAttributeMaxDynamicSharedMemorySize,
                         smem_bytes);
    dim3 agrid(LL / 64, HH, BB);
    attn_kernel<<<agrid, 256, smem_bytes>>>(out);
}

// round 4
// speedup vs baseline: 1.2420x; 1.2420x over previous
#include <cuda_runtime.h>
#include <cuda_bf16.h>
#include <math.h>
#include <stdint.h>

#define BB 2
#define LL 2048
#define DD 1024
#define HH 16
#define HDIM 64
#define D3 3072
#define RLEN 4095   // 2*L - 1
#define MTOT 4096   // B*L
#define K2 2048     // hi|lo concatenated K

// Scratch (no allocation allowed)
__device__ __align__(1024) float g_proj[(size_t)BB * LL * D3];
__device__ float g_scores[HH * RLEN];
__device__ __align__(1024) __nv_bfloat16 g_Abig[(size_t)MTOT * K2];  // x  hi|lo
__device__ __align__(1024) __nv_bfloat16 g_Bbig[(size_t)D3 * K2];    // w  hi|lo

__device__ __forceinline__ uint32_t smem_to_u32(const void* p) {
    uint32_t a;
    asm("{ .reg .u64 t; cvta.to.shared.u64 t, %1; cvt.u32.u64 %0, t; }"
        : "=r"(a) : "l"(p));
    return a;
}

// ---------------------------------------------------------------------------
// Kernel 1: TISA bias table
// ---------------------------------------------------------------------------
__global__ __launch_bounds__(256) void scores_kernel(const float* __restrict__ off,
                                                     const float* __restrict__ amp,
                                                     const float* __restrict__ shp)
{
    int h = blockIdx.x;
    __shared__ float so[16], sa[16], ss[16];
    if (threadIdx.x < 16) {
        so[threadIdx.x] = off[h * 16 + threadIdx.x];
        sa[threadIdx.x] = amp[h * 16 + threadIdx.x];
        ss[threadIdx.x] = fabsf(shp[h * 16 + threadIdx.x]);
    }
    __syncthreads();
    for (int r = threadIdx.x; r < RLEN; r += blockDim.x) {
        float rel = (float)(r - (LL - 1));
        float acc = 0.f;
#pragma unroll
        for (int k = 0; k < 16; k++) {
            float d = so[k] - rel;
            acc += sa[k] * expf(-ss[k] * d * d);
        }
        g_scores[h * RLEN + r] = acc;
    }
}

// ---------------------------------------------------------------------------
// Kernel 2a: fp32 -> bf16 hi/lo split. dst rows of K2: [hi(0..1023) | lo(1024..2047)]
// ---------------------------------------------------------------------------
__global__ __launch_bounds__(256) void convert_kernel(const float* __restrict__ src,
                                                      __nv_bfloat16* __restrict__ dst)
{
    int idx = blockIdx.x * 256 + threadIdx.x;
    int row = idx >> 8;
    int k = (idx & 255) << 2;
    float4 v = *(const float4*)(src + (size_t)row * DD + k);
    __nv_bfloat16 h0 = __float2bfloat16_rn(v.x);
    __nv_bfloat16 h1 = __float2bfloat16_rn(v.y);
    __nv_bfloat16 h2 = __float2bfloat16_rn(v.z);
    __nv_bfloat16 h3 = __float2bfloat16_rn(v.w);
    __nv_bfloat16 l0 = __float2bfloat16_rn(v.x - __bfloat162float(h0));
    __nv_bfloat16 l1 = __float2bfloat16_rn(v.y - __bfloat162float(h1));
    __nv_bfloat16 l2 = __float2bfloat16_rn(v.z - __bfloat162float(h2));
    __nv_bfloat16 l3 = __float2bfloat16_rn(v.w - __bfloat162float(h3));
    __nv_bfloat162* dh = (__nv_bfloat162*)(dst + (size_t)row * K2 + k);
    dh[0] = __nv_bfloat162(h0, h1);
    dh[1] = __nv_bfloat162(h2, h3);
    __nv_bfloat162* dl = (__nv_bfloat162*)(dst + (size_t)row * K2 + DD + k);
    dl[0] = __nv_bfloat162(l0, l1);
    dl[1] = __nv_bfloat162(l2, l3);
}

// ---------------------------------------------------------------------------
// Kernel 2b: HMMA (mma.sync bf16) split GEMM: g_proj[m][n] = sum_k x[m][k]*w[n][k]
// CTA tile 128x128, 8 warps (4M x 2N), warp tile 32x64, BK=64 bf16.
// 3-stage cp.async pipeline, XOR-swizzled smem, fp32 register accumulators.
// 48 chunks: 16x Ahi*Bhi, 16x Ahi*Blo, 16x Alo*Bhi.
// ---------------------------------------------------------------------------
#define NCHUNK 48
#define STG_BYTES 32768   // per stage: A 16KB + B 16KB

__device__ __forceinline__ void load_chunk(uint32_t sA, uint32_t sB,
                                           const __nv_bfloat16* __restrict__ gA,
                                           const __nv_bfloat16* __restrict__ gB,
                                           int bm, int bn, int ka, int kb, int tid)
{
#pragma unroll
    for (int i = 0; i < 4; i++) {
        int s = tid + i * 256;
        int row = s >> 3, kseg = s & 7;
        uint32_t dst = sA + row * 128 + ((kseg ^ (row & 7)) << 4);
        const void* src = gA + (size_t)(bm + row) * K2 + ka + kseg * 8;
        asm volatile("cp.async.cg.shared.global [%0], [%1], 16;" :: "r"(dst), "l"(src));
    }
#pragma unroll
    for (int i = 0; i < 4; i++) {
        int s = tid + i * 256;
        int row = s >> 3, kseg = s & 7;
        uint32_t dst = sB + row * 128 + ((kseg ^ (row & 7)) << 4);
        const void* src = gB + (size_t)(bn + row) * K2 + kb + kseg * 8;
        asm volatile("cp.async.cg.shared.global [%0], [%1], 16;" :: "r"(dst), "l"(src));
    }
    asm volatile("cp.async.commit_group;" ::: "memory");
}

__global__ __launch_bounds__(256) void proj_mma()
{
    extern __shared__ char smem[];
    const uint32_t sbase = smem_to_u32(smem);
    const int tid = threadIdx.x;
    const int wid = tid >> 5, lane = tid & 31;
    const int bm = blockIdx.y * 128, bn = blockIdx.x * 128;
    const int wm = (wid >> 1) * 32;   // warp M offset within CTA tile
    const int wn = (wid & 1) * 64;    // warp N offset

    float acc[2][8][4];
#pragma unroll
    for (int mt = 0; mt < 2; mt++)
#pragma unroll
        for (int nt = 0; nt < 8; nt++)
#pragma unroll
            for (int c = 0; c < 4; c++) acc[mt][nt][c] = 0.f;

    // chunk t -> (ka, kb)
    auto kamap = [](int t, int& ka, int& kb) {
        int pass = t >> 4, kt = t & 15;
        ka = (pass == 2) ? (DD + kt * 64) : (kt * 64);
        kb = (pass == 1) ? (DD + kt * 64) : (kt * 64);
    };

    {
        int ka, kb;
        kamap(0, ka, kb);
        load_chunk(sbase, sbase + 16384, g_Abig, g_Bbig, bm, bn, ka, kb, tid);
        kamap(1, ka, kb);
        load_chunk(sbase + STG_BYTES, sbase + STG_BYTES + 16384, g_Abig, g_Bbig,
                   bm, bn, ka, kb, tid);
    }

    for (int t = 0; t < NCHUNK; t++) {
        asm volatile("cp.async.wait_group 1;" ::: "memory");
        __syncthreads();

        if (t + 2 < NCHUNK) {
            int ka, kb;
            kamap(t + 2, ka, kb);
            uint32_t s = sbase + ((t + 2) % 3) * STG_BYTES;
            load_chunk(s, s + 16384, g_Abig, g_Bbig, bm, bn, ka, kb, tid);
        } else {
            asm volatile("cp.async.commit_group;" ::: "memory");
        }

        const uint32_t sA = sbase + (t % 3) * STG_BYTES;
        const uint32_t sB = sA + 16384;

#pragma unroll
        for (int kk = 0; kk < 4; kk++) {
            uint32_t a[2][4];
#pragma unroll
            for (int mt = 0; mt < 2; mt++) {
                int row = wm + mt * 16 + (lane & 15);
                int kseg = kk * 2 + (lane >> 4);
                uint32_t addr = sA + row * 128 + ((kseg ^ (row & 7)) << 4);
                asm volatile("ldmatrix.sync.aligned.m8n8.x4.shared.b16 "
                             "{%0, %1, %2, %3}, [%4];"
                             : "=r"(a[mt][0]), "=r"(a[mt][1]),
                               "=r"(a[mt][2]), "=r"(a[mt][3])
                             : "r"(addr));
            }
            uint32_t b[8][2];
#pragma unroll
            for (int p = 0; p < 4; p++) {   // pair of n8 tiles per ldmatrix.x4
                int row = wn + p * 16 + (lane & 7) + ((lane >> 4) << 3);
                int kseg = kk * 2 + ((lane >> 3) & 1);
                uint32_t addr = sB + row * 128 + ((kseg ^ (row & 7)) << 4);
                asm volatile("ldmatrix.sync.aligned.m8n8.x4.shared.b16 "
                             "{%0, %1, %2, %3}, [%4];"
                             : "=r"(b[2 * p][0]), "=r"(b[2 * p][1]),
                               "=r"(b[2 * p + 1][0]), "=r"(b[2 * p + 1][1])
                             : "r"(addr));
            }
#pragma unroll
            for (int mt = 0; mt < 2; mt++)
#pragma unroll
                for (int nt = 0; nt < 8; nt++) {
                    asm volatile(
                        "mma.sync.aligned.m16n8k16.row.col.f32.bf16.bf16.f32 "
                        "{%0, %1, %2, %3}, {%4, %5, %6, %7}, {%8, %9}, "
                        "{%0, %1, %2, %3};"
                        : "+f"(acc[mt][nt][0]), "+f"(acc[mt][nt][1]),
                          "+f"(acc[mt][nt][2]), "+f"(acc[mt][nt][3])
                        : "r"(a[mt][0]), "r"(a[mt][1]), "r"(a[mt][2]), "r"(a[mt][3]),
                          "r"(b[nt][0]), "r"(b[nt][1]));
                }
        }
        __syncthreads();
    }

    // Epilogue: fp32 to g_proj
#pragma unroll
    for (int mt = 0; mt < 2; mt++) {
        int row0 = bm + wm + mt * 16 + (lane >> 2);
#pragma unroll
        for (int nt = 0; nt < 8; nt++) {
            int col = bn + wn + nt * 8 + (lane & 3) * 2;
            *(float2*)(g_proj + (size_t)row0 * D3 + col) =
                make_float2(acc[mt][nt][0], acc[mt][nt][1]);
            *(float2*)(g_proj + (size_t)(row0 + 8) * D3 + col) =
                make_float2(acc[mt][nt][2], acc[mt][nt][3]);
        }
    }
}

// ---------------------------------------------------------------------------
// Kernel 3: flash attention with TISA bias (fp32 FMA — R4 target)
// ---------------------------------------------------------------------------
__global__ __launch_bounds__(256) void attn_kernel(float* __restrict__ out)
{
    extern __shared__ float sm[];
    float* Qs = sm;               // [64][64]
    float* Ks = Qs + 64 * 64;     // [64][68] padded
    float* Vs = Ks + 64 * 68;     // [64][64]
    float* Ps = Vs + 64 * 64;     // [64][65] padded
    float* sb = Ps + 64 * 65;     // [128] bias diagonal slice

    const int qb = blockIdx.x * 64;
    const int h  = blockIdx.y;
    const int b  = blockIdx.z;
    const int tid = threadIdx.x;
    const int tx = tid & 15, ty = tid >> 4;

    const float* base = g_proj + (size_t)b * LL * D3;
    const float* kptr = base + h * HDIM;
    const float* vptr = base + DD + h * HDIM;
    const float* qptr = base + 2 * DD + h * HDIM;
    const float* srow = g_scores + h * RLEN;
    const float scale = 0.125f;

    for (int i = tid; i < 1024; i += 256) {
        int r = i >> 4;
        int d = (i & 15) << 2;
        float4 v = *(const float4*)(qptr + (size_t)(qb + r) * D3 + d);
        *(float4*)(Qs + r * 64 + d) = v;
    }

    float m_run[4], l_run[4], O[4][4];
#pragma unroll
    for (int i = 0; i < 4; i++) {
        m_run[i] = -3.0e38f; l_run[i] = 0.f;
#pragma unroll
        for (int j = 0; j < 4; j++) O[i][j] = 0.f;
    }

    for (int kb = 0; kb < LL; kb += 64) {
        __syncthreads();
        for (int i = tid; i < 1024; i += 256) {
            int r = i >> 4;
            int d = (i & 15) << 2;
            float4 kv = *(const float4*)(kptr + (size_t)(kb + r) * D3 + d);
            Ks[r * 68 + d + 0] = kv.x;
            Ks[r * 68 + d + 1] = kv.y;
            Ks[r * 68 + d + 2] = kv.z;
            Ks[r * 68 + d + 3] = kv.w;
            float4 vv = *(const float4*)(vptr + (size_t)(kb + r) * D3 + d);
            *(float4*)(Vs + r * 64 + d) = vv;
        }
        if (tid < 127) sb[tid] = srow[qb - kb + 2047 - 63 + tid];
        __syncthreads();

        float S[4][4];
#pragma unroll
        for (int i = 0; i < 4; i++)
#pragma unroll
            for (int j = 0; j < 4; j++) S[i][j] = 0.f;

#pragma unroll
        for (int d4 = 0; d4 < 16; d4++) {
            float4 rq[4], rk[4];
#pragma unroll
            for (int i = 0; i < 4; i++)
                rq[i] = *(const float4*)(Qs + (ty + 16 * i) * 64 + d4 * 4);
#pragma unroll
            for (int j = 0; j < 4; j++)
                rk[j] = *(const float4*)(Ks + (tx + 16 * j) * 68 + d4 * 4);
#pragma unroll
            for (int i = 0; i < 4; i++)
#pragma unroll
                for (int j = 0; j < 4; j++) {
                    S[i][j] = fmaf(rq[i].x, rk[j].x, S[i][j]);
                    S[i][j] = fmaf(rq[i].y, rk[j].y, S[i][j]);
                    S[i][j] = fmaf(rq[i].z, rk[j].z, S[i][j]);
                    S[i][j] = fmaf(rq[i].w, rk[j].w, S[i][j]);
                }
        }

#pragma unroll
        for (int i = 0; i < 4; i++) {
            float mx = -3.0e38f;
#pragma unroll
            for (int j = 0; j < 4; j++) {
                S[i][j] = S[i][j] * scale + sb[(ty + 16 * i) - (tx + 16 * j) + 63];
                mx = fmaxf(mx, S[i][j]);
            }
#pragma unroll
            for (int s = 8; s > 0; s >>= 1)
                mx = fmaxf(mx, __shfl_xor_sync(0xffffffffu, mx, s, 16));
            float mnew = fmaxf(m_run[i], mx);
            float corr = __expf(m_run[i] - mnew);
            m_run[i] = mnew;
            float rs = 0.f;
#pragma unroll
            for (int j = 0; j < 4; j++) {
                float p = __expf(S[i][j] - mnew);
                Ps[(ty + 16 * i) * 65 + (tx + 16 * j)] = p;
                rs += p;
            }
#pragma unroll
            for (int s = 8; s > 0; s >>= 1)
                rs += __shfl_xor_sync(0xffffffffu, rs, s, 16);
            l_run[i] = l_run[i] * corr + rs;
#pragma unroll
            for (int j = 0; j < 4; j++) O[i][j] *= corr;
        }
        __syncthreads();

#pragma unroll 8
        for (int kv = 0; kv < 64; kv++) {
            float pv[4];
#pragma unroll
            for (int i = 0; i < 4; i++) pv[i] = Ps[(ty + 16 * i) * 65 + kv];
            float4 vv = *(const float4*)(Vs + kv * 64 + tx * 4);
#pragma unroll
            for (int i = 0; i < 4; i++) {
                O[i][0] = fmaf(pv[i], vv.x, O[i][0]);
                O[i][1] = fmaf(pv[i], vv.y, O[i][1]);
                O[i][2] = fmaf(pv[i], vv.z, O[i][2]);
                O[i][3] = fmaf(pv[i], vv.w, O[i][3]);
            }
        }
    }

#pragma unroll
    for (int i = 0; i < 4; i++) {
        float inv = 1.0f / l_run[i];
        float4 o = make_float4(O[i][0] * inv, O[i][1] * inv, O[i][2] * inv, O[i][3] * inv);
        size_t row = (size_t)(b * LL + qb + ty + 16 * i);
        *(float4*)(out + row * DD + h * HDIM + tx * 4) = o;
    }
}

// ---------------------------------------------------------------------------
extern "C" void kernel_launch(void* const* d_in, const int* in_sizes, int n_in,
                              void* d_out, int out_size)
{
    const float* x    = (const float*)d_in[0];
    const float* w_in = (const float*)d_in[1];
    const float* off  = (const float*)d_in[2];
    const float* amp  = (const float*)d_in[3];
    const float* shp  = (const float*)d_in[4];
    float* out = (float*)d_out;

    scores_kernel<<<HH, 256>>>(off, amp, shp);

    // bf16 hi/lo split of x and w_in
    {
        __nv_bfloat16* abig;
        __nv_bfloat16* bbig;
        cudaGetSymbolAddress((void**)&abig, g_Abig);
        cudaGetSymbolAddress((void**)&bbig, g_Bbig);
        convert_kernel<<<(MTOT * DD / 4) / 256, 256>>>(x, abig);
        convert_kernel<<<(D3 * DD / 4) / 256, 256>>>(w_in, bbig);
    }

    // HMMA projection GEMM
    {
        const int smem_bytes = 3 * STG_BYTES;  // 98304
        cudaFuncSetAttribute(proj_mma, cudaFuncAttributeMaxDynamicSharedMemorySize,
                             smem_bytes);
        dim3 grid(D3 / 128, MTOT / 128);
        proj_mma<<<grid, 256, smem_bytes>>>();
    }

    // attention (fp32)
    {
        const int smem_bytes = (64 * 64 + 64 * 68 + 64 * 64 + 64 * 65 + 128) * 4;
        cudaFuncSetAttribute(attn_kernel, cudaFuncAttributeMaxDynamicSharedMemorySize,
                             smem_bytes);
        dim3 agrid(LL / 64, HH, BB);
        attn_kernel<<<agrid, 256, smem_bytes>>>(out);
    }
}

// round 5
// speedup vs baseline: 2.7579x; 2.2206x over previous
#include <cuda_runtime.h>
#include <cuda_bf16.h>
#include <math.h>
#include <stdint.h>

#define BB 2
#define LL 2048
#define DD 1024
#define HH 16
#define HDIM 64
#define D3 3072
#define RLEN 4095   // 2*L - 1
#define MTOT 4096   // B*L
#define K2 2048     // hi|lo concatenated K

// Scratch (no allocation allowed)
__device__ float g_scores[HH * RLEN];
__device__ __align__(1024) __nv_bfloat16 g_Abig[(size_t)MTOT * K2];  // x  hi|lo
__device__ __align__(1024) __nv_bfloat16 g_Bbig[(size_t)D3 * K2];    // w  hi|lo
// Per-head bf16 hi/lo tensors: [b][h][l][64]
#define HSZ ((size_t)BB * HH * LL * HDIM)
__device__ __align__(1024) __nv_bfloat16 g_Qh[HSZ];
__device__ __align__(1024) __nv_bfloat16 g_Ql[HSZ];
__device__ __align__(1024) __nv_bfloat16 g_Kh[HSZ];
__device__ __align__(1024) __nv_bfloat16 g_Kl[HSZ];
__device__ __align__(1024) __nv_bfloat16 g_Vh[HSZ];
__device__ __align__(1024) __nv_bfloat16 g_Vl[HSZ];

__device__ __forceinline__ uint32_t smem_to_u32(const void* p) {
    uint32_t a;
    asm("{ .reg .u64 t; cvta.to.shared.u64 t, %1; cvt.u32.u64 %0, t; }"
        : "=r"(a) : "l"(p));
    return a;
}
#define CP16(dst, src) \
    asm volatile("cp.async.cg.shared.global [%0], [%1], 16;" :: "r"(dst), "l"(src))
#define CP_COMMIT() asm volatile("cp.async.commit_group;" ::: "memory")
#define CP_WAIT0() asm volatile("cp.async.wait_group 0;" ::: "memory")
#define CP_WAIT1() asm volatile("cp.async.wait_group 1;" ::: "memory")

__device__ __forceinline__ void ldsm4(uint32_t* r, uint32_t addr) {
    asm volatile("ldmatrix.sync.aligned.m8n8.x4.shared.b16 {%0, %1, %2, %3}, [%4];"
                 : "=r"(r[0]), "=r"(r[1]), "=r"(r[2]), "=r"(r[3]) : "r"(addr));
}
__device__ __forceinline__ void ldsm4t(uint32_t* r, uint32_t addr) {
    asm volatile("ldmatrix.sync.aligned.m8n8.x4.trans.shared.b16 {%0, %1, %2, %3}, [%4];"
                 : "=r"(r[0]), "=r"(r[1]), "=r"(r[2]), "=r"(r[3]) : "r"(addr));
}
__device__ __forceinline__ void mma16816(float* c, const uint32_t* a, const uint32_t* b) {
    asm volatile("mma.sync.aligned.m16n8k16.row.col.f32.bf16.bf16.f32 "
                 "{%0, %1, %2, %3}, {%4, %5, %6, %7}, {%8, %9}, {%0, %1, %2, %3};"
                 : "+f"(c[0]), "+f"(c[1]), "+f"(c[2]), "+f"(c[3])
                 : "r"(a[0]), "r"(a[1]), "r"(a[2]), "r"(a[3]), "r"(b[0]), "r"(b[1]));
}
// packed bf16x2: low = lo, high = hi
__device__ __forceinline__ uint32_t packbf(float lo, float hi) {
    uint32_t r;
    asm("cvt.rn.bf16x2.f32 %0, %1, %2;" : "=r"(r) : "f"(hi), "f"(lo));
    return r;
}

// ---------------------------------------------------------------------------
// Kernel 1: TISA bias table
// ---------------------------------------------------------------------------
__global__ __launch_bounds__(256) void scores_kernel(const float* __restrict__ off,
                                                     const float* __restrict__ amp,
                                                     const float* __restrict__ shp)
{
    int h = blockIdx.x;
    __shared__ float so[16], sa[16], ss[16];
    if (threadIdx.x < 16) {
        so[threadIdx.x] = off[h * 16 + threadIdx.x];
        sa[threadIdx.x] = amp[h * 16 + threadIdx.x];
        ss[threadIdx.x] = fabsf(shp[h * 16 + threadIdx.x]);
    }
    __syncthreads();
    for (int r = threadIdx.x; r < RLEN; r += blockDim.x) {
        float rel = (float)(r - (LL - 1));
        float acc = 0.f;
#pragma unroll
        for (int k = 0; k < 16; k++) {
            float d = so[k] - rel;
            acc += sa[k] * expf(-ss[k] * d * d);
        }
        g_scores[h * RLEN + r] = acc;
    }
}

// ---------------------------------------------------------------------------
// Kernel 2a: fp32 -> bf16 hi/lo split for GEMM inputs
// ---------------------------------------------------------------------------
__global__ __launch_bounds__(256) void convert_kernel(const float* __restrict__ src,
                                                      __nv_bfloat16* __restrict__ dst)
{
    int idx = blockIdx.x * 256 + threadIdx.x;
    int row = idx >> 8;
    int k = (idx & 255) << 2;
    float4 v = *(const float4*)(src + (size_t)row * DD + k);
    __nv_bfloat16 h0 = __float2bfloat16_rn(v.x);
    __nv_bfloat16 h1 = __float2bfloat16_rn(v.y);
    __nv_bfloat16 h2 = __float2bfloat16_rn(v.z);
    __nv_bfloat16 h3 = __float2bfloat16_rn(v.w);
    __nv_bfloat16 l0 = __float2bfloat16_rn(v.x - __bfloat162float(h0));
    __nv_bfloat16 l1 = __float2bfloat16_rn(v.y - __bfloat162float(h1));
    __nv_bfloat16 l2 = __float2bfloat16_rn(v.z - __bfloat162float(h2));
    __nv_bfloat16 l3 = __float2bfloat16_rn(v.w - __bfloat162float(h3));
    __nv_bfloat162* dh = (__nv_bfloat162*)(dst + (size_t)row * K2 + k);
    dh[0] = __nv_bfloat162(h0, h1);
    dh[1] = __nv_bfloat162(h2, h3);
    __nv_bfloat162* dl = (__nv_bfloat162*)(dst + (size_t)row * K2 + DD + k);
    dl[0] = __nv_bfloat162(l0, l1);
    dl[1] = __nv_bfloat162(l2, l3);
}

// ---------------------------------------------------------------------------
// Kernel 2b: HMMA split GEMM, epilogue writes per-head bf16 hi/lo q,k,v.
// CTA 128x128, 8 warps (4M x 2N), warp tile 32x64, BK=64, 3-stage cp.async.
// ---------------------------------------------------------------------------
#define NCHUNK 48
#define STG_BYTES 32768

__device__ __forceinline__ void load_chunk(uint32_t sA, uint32_t sB,
                                           const __nv_bfloat16* __restrict__ gA,
                                           const __nv_bfloat16* __restrict__ gB,
                                           int bm, int bn, int ka, int kb, int tid)
{
#pragma unroll
    for (int i = 0; i < 4; i++) {
        int s = tid + i * 256;
        int row = s >> 3, kseg = s & 7;
        uint32_t dst = sA + row * 128 + ((kseg ^ (row & 7)) << 4);
        const void* src = gA + (size_t)(bm + row) * K2 + ka + kseg * 8;
        CP16(dst, src);
    }
#pragma unroll
    for (int i = 0; i < 4; i++) {
        int s = tid + i * 256;
        int row = s >> 3, kseg = s & 7;
        uint32_t dst = sB + row * 128 + ((kseg ^ (row & 7)) << 4);
        const void* src = gB + (size_t)(bn + row) * K2 + kb + kseg * 8;
        CP16(dst, src);
    }
    CP_COMMIT();
}

__global__ __launch_bounds__(256) void proj_mma()
{
    extern __shared__ char smem[];
    const uint32_t sbase = smem_to_u32(smem);
    const int tid = threadIdx.x;
    const int wid = tid >> 5, lane = tid & 31;
    const int bm = blockIdx.y * 128, bn = blockIdx.x * 128;
    const int wm = (wid >> 1) * 32;
    const int wn = (wid & 1) * 64;

    float acc[2][8][4];
#pragma unroll
    for (int mt = 0; mt < 2; mt++)
#pragma unroll
        for (int nt = 0; nt < 8; nt++)
#pragma unroll
            for (int c = 0; c < 4; c++) acc[mt][nt][c] = 0.f;

    auto kamap = [](int t, int& ka, int& kb) {
        int pass = t >> 4, kt = t & 15;
        ka = (pass == 2) ? (DD + kt * 64) : (kt * 64);
        kb = (pass == 1) ? (DD + kt * 64) : (kt * 64);
    };

    {
        int ka, kb;
        kamap(0, ka, kb);
        load_chunk(sbase, sbase + 16384, g_Abig, g_Bbig, bm, bn, ka, kb, tid);
        kamap(1, ka, kb);
        load_chunk(sbase + STG_BYTES, sbase + STG_BYTES + 16384, g_Abig, g_Bbig,
                   bm, bn, ka, kb, tid);
    }

    for (int t = 0; t < NCHUNK; t++) {
        CP_WAIT1();
        __syncthreads();

        if (t + 2 < NCHUNK) {
            int ka, kb;
            kamap(t + 2, ka, kb);
            uint32_t s = sbase + ((t + 2) % 3) * STG_BYTES;
            load_chunk(s, s + 16384, g_Abig, g_Bbig, bm, bn, ka, kb, tid);
        } else {
            CP_COMMIT();
        }

        const uint32_t sA = sbase + (t % 3) * STG_BYTES;
        const uint32_t sB = sA + 16384;

#pragma unroll
        for (int kk = 0; kk < 4; kk++) {
            uint32_t a[2][4];
#pragma unroll
            for (int mt = 0; mt < 2; mt++) {
                int row = wm + mt * 16 + (lane & 15);
                int kseg = kk * 2 + (lane >> 4);
                uint32_t addr = sA + row * 128 + ((kseg ^ (row & 7)) << 4);
                ldsm4(a[mt], addr);
            }
            uint32_t b[8][2];
#pragma unroll
            for (int p = 0; p < 4; p++) {
                int row = wn + p * 16 + (lane & 7) + ((lane >> 4) << 3);
                int kseg = kk * 2 + ((lane >> 3) & 1);
                uint32_t addr = sB + row * 128 + ((kseg ^ (row & 7)) << 4);
                ldsm4(&b[2 * p][0], addr);
            }
#pragma unroll
            for (int mt = 0; mt < 2; mt++)
#pragma unroll
                for (int nt = 0; nt < 8; nt++)
                    mma16816(acc[mt][nt], a[mt], b[nt]);
        }
        __syncthreads();
    }

    // Epilogue: split each value into bf16 hi/lo, write to per-head q/k/v arrays.
#pragma unroll
    for (int mt = 0; mt < 2; mt++) {
        int row0 = bm + wm + mt * 16 + (lane >> 2);
        int b = row0 >> 11;
        int l = row0 & 2047;
#pragma unroll
        for (int nt = 0; nt < 8; nt++) {
            int col = bn + wn + nt * 8 + (lane & 3) * 2;
            int ty = col >> 10;            // 0=k, 1=v, 2=q
            int h = (col >> 6) & 15;
            int d = col & 63;
            float sc = (ty == 2) ? 0.125f : 1.0f;
            float v0 = acc[mt][nt][0] * sc, v1 = acc[mt][nt][1] * sc;
            float v2 = acc[mt][nt][2] * sc, v3 = acc[mt][nt][3] * sc;
            uint32_t h01 = packbf(v0, v1), h23 = packbf(v2, v3);
            float q0 = __uint_as_float(h01 << 16);
            float q1 = __uint_as_float(h01 & 0xFFFF0000u);
            float q2 = __uint_as_float(h23 << 16);
            float q3 = __uint_as_float(h23 & 0xFFFF0000u);
            uint32_t l01 = packbf(v0 - q0, v1 - q1);
            uint32_t l23 = packbf(v2 - q2, v3 - q3);
            __nv_bfloat16 *dh, *dl;
            if (ty == 0)      { dh = g_Kh; dl = g_Kl; }
            else if (ty == 1) { dh = g_Vh; dl = g_Vl; }
            else              { dh = g_Qh; dl = g_Ql; }
            size_t base0 = ((size_t)(b * HH + h) * LL + l) * HDIM + d;
            size_t base1 = base0 + 8 * HDIM;
            *(uint32_t*)(dh + base0) = h01;
            *(uint32_t*)(dl + base0) = l01;
            *(uint32_t*)(dh + base1) = h23;
            *(uint32_t*)(dl + base1) = l23;
        }
    }
}

// ---------------------------------------------------------------------------
// Kernel 3: HMMA flash attention with TISA bias, hi/lo split throughout.
// CTA = 128 queries x (b,h). 8 warps x m16. kv tiles of 64, double-buffered.
// smem: stage s at s*32768: Khi|Klo|Vhi|Vlo (8KB each). bias sb[2][192] @65536.
// ---------------------------------------------------------------------------
__device__ __forceinline__ void attn_load_kv(uint32_t sbase, int stage, int bh,
                                             int kb, int tid)
{
    uint32_t stg = sbase + stage * 32768;
#pragma unroll
    for (int i = 0; i < 8; i++) {
        const int comp = i >> 1;
        int row = (tid >> 3) + 32 * (i & 1);
        int kseg = tid & 7;
        const __nv_bfloat16* gb = (comp == 0) ? g_Kh : (comp == 1) ? g_Kl
                                 : (comp == 2) ? g_Vh : g_Vl;
        uint32_t dst = stg + comp * 8192 + row * 128 + ((kseg ^ (row & 7)) << 4);
        const void* src = gb + ((size_t)bh * LL + kb + row) * HDIM + kseg * 8;
        CP16(dst, src);
    }
    CP_COMMIT();
}

__global__ __launch_bounds__(256) void attn_mma(float* __restrict__ out)
{
    extern __shared__ char smem[];
    const uint32_t sbase = smem_to_u32(smem);
    float* sb = (float*)(smem + 65536);   // [2][192]
    const int tid = threadIdx.x;
    const int wid = tid >> 5, lane = tid & 31;
    const int gid = lane >> 2, tg = lane & 3;
    const int qb = blockIdx.x * 128;
    const int h = blockIdx.y, b = blockIdx.z;
    const int bh = b * HH + h;
    const int wm = wid * 16;
    const float* srow = g_scores + h * RLEN;

    // --- Prologue: load Q (hi@0, lo@16384 in stage0 space), ldmatrix to regs
#pragma unroll
    for (int i = 0; i < 8; i++) {
        const int comp = i >> 2;
        int row = (tid >> 3) + 32 * (i & 3);
        int kseg = tid & 7;
        const __nv_bfloat16* gb = comp ? g_Ql : g_Qh;
        uint32_t dst = sbase + comp * 16384 + row * 128 + ((kseg ^ (row & 7)) << 4);
        const void* src = gb + ((size_t)bh * LL + qb + row) * HDIM + kseg * 8;
        CP16(dst, src);
    }
    CP_COMMIT();
    CP_WAIT0();
    __syncthreads();

    uint32_t aQh[4][4], aQl[4][4];
#pragma unroll
    for (int ks = 0; ks < 4; ks++) {
        int row = wm + (lane & 15);
        int kseg = ks * 2 + (lane >> 4);
        uint32_t sw = row * 128 + ((kseg ^ (row & 7)) << 4);
        ldsm4(aQh[ks], sbase + sw);
        ldsm4(aQl[ks], sbase + 16384 + sw);
    }
    __syncthreads();

    attn_load_kv(sbase, 0, bh, 0, tid);
    if (tid < 192) {
        int sidx = qb + 1984 + tid;
        sb[tid] = srow[min(sidx, RLEN - 1)];
    }

    float O[8][4];
#pragma unroll
    for (int nt = 0; nt < 8; nt++)
#pragma unroll
        for (int c = 0; c < 4; c++) O[nt][c] = 0.f;
    float m0 = -1e30f, m1 = -1e30f, l0 = 0.f, l1 = 0.f;

    for (int t = 0; t < LL / 64; t++) {
        CP_WAIT0();
        __syncthreads();
        const uint32_t stg = sbase + (t & 1) * 32768;
        const float* sbt = sb + (t & 1) * 192;

        if (t + 1 < LL / 64) {
            attn_load_kv(sbase, (t + 1) & 1, bh, (t + 1) * 64, tid);
            if (tid < 192) {
                int sidx = qb - (t + 1) * 64 + 1984 + tid;
                sb[((t + 1) & 1) * 192 + tid] = srow[min(sidx, RLEN - 1)];
            }
        }

        // ---- S = Q K^T (3-pass split), fp32 accum
        float S[8][4];
#pragma unroll
        for (int nt = 0; nt < 8; nt++)
#pragma unroll
            for (int c = 0; c < 4; c++) S[nt][c] = 0.f;

#pragma unroll
        for (int kk = 0; kk < 4; kk++) {
            uint32_t kf[8][2];
            int krow = (lane & 7) + ((lane >> 4) << 3);
            int kkseg = kk * 2 + ((lane >> 3) & 1);
#pragma unroll
            for (int p = 0; p < 4; p++) {
                int row = krow + p * 16;
                uint32_t addr = stg + row * 128 + ((kkseg ^ (row & 7)) << 4);
                ldsm4(&kf[2 * p][0], addr);
            }
#pragma unroll
            for (int nt = 0; nt < 8; nt++) {
                mma16816(S[nt], aQh[kk], kf[nt]);
                mma16816(S[nt], aQl[kk], kf[nt]);
            }
#pragma unroll
            for (int p = 0; p < 4; p++) {
                int row = krow + p * 16;
                uint32_t addr = stg + 8192 + row * 128 + ((kkseg ^ (row & 7)) << 4);
                ldsm4(&kf[2 * p][0], addr);
            }
#pragma unroll
            for (int nt = 0; nt < 8; nt++)
                mma16816(S[nt], aQh[kk], kf[nt]);
        }

        // ---- bias + online softmax
        const int jbase = wm + gid + 63 - 2 * tg;
        float mx0 = -1e30f, mx1 = -1e30f;
#pragma unroll
        for (int nt = 0; nt < 8; nt++) {
            int j = jbase - 8 * nt;
            S[nt][0] += sbt[j];
            S[nt][1] += sbt[j - 1];
            S[nt][2] += sbt[j + 8];
            S[nt][3] += sbt[j + 7];
            mx0 = fmaxf(mx0, fmaxf(S[nt][0], S[nt][1]));
            mx1 = fmaxf(mx1, fmaxf(S[nt][2], S[nt][3]));
        }
        mx0 = fmaxf(mx0, __shfl_xor_sync(0xffffffffu, mx0, 1));
        mx0 = fmaxf(mx0, __shfl_xor_sync(0xffffffffu, mx0, 2));
        mx1 = fmaxf(mx1, __shfl_xor_sync(0xffffffffu, mx1, 1));
        mx1 = fmaxf(mx1, __shfl_xor_sync(0xffffffffu, mx1, 2));
        float nm0 = fmaxf(m0, mx0), nm1 = fmaxf(m1, mx1);
        float c0 = __expf(m0 - nm0), c1 = __expf(m1 - nm1);
        m0 = nm0; m1 = nm1;

        float rs0 = 0.f, rs1 = 0.f;
        uint32_t aPh[4][4], aPl[4][4];
#pragma unroll
        for (int nt = 0; nt < 8; nt++) {
            float p0 = __expf(S[nt][0] - nm0);
            float p1 = __expf(S[nt][1] - nm0);
            float p2 = __expf(S[nt][2] - nm1);
            float p3 = __expf(S[nt][3] - nm1);
            rs0 += p0 + p1;
            rs1 += p2 + p3;
            uint32_t h01 = packbf(p0, p1), h23 = packbf(p2, p3);
            float q0 = __uint_as_float(h01 << 16);
            float q1 = __uint_as_float(h01 & 0xFFFF0000u);
            float q2 = __uint_as_float(h23 << 16);
            float q3 = __uint_as_float(h23 & 0xFFFF0000u);
            uint32_t l01 = packbf(p0 - q0, p1 - q1);
            uint32_t l23 = packbf(p2 - q2, p3 - q3);
            int ks = nt >> 1, hf = (nt & 1) * 2;
            aPh[ks][hf] = h01; aPh[ks][hf + 1] = h23;
            aPl[ks][hf] = l01; aPl[ks][hf + 1] = l23;
        }
        rs0 += __shfl_xor_sync(0xffffffffu, rs0, 1);
        rs0 += __shfl_xor_sync(0xffffffffu, rs0, 2);
        rs1 += __shfl_xor_sync(0xffffffffu, rs1, 1);
        rs1 += __shfl_xor_sync(0xffffffffu, rs1, 2);
        l0 = l0 * c0 + rs0;
        l1 = l1 * c1 + rs1;
#pragma unroll
        for (int nt = 0; nt < 8; nt++) {
            O[nt][0] *= c0; O[nt][1] *= c0;
            O[nt][2] *= c1; O[nt][3] *= c1;
        }

        // ---- O += P V (3-pass split), V frags via ldmatrix.trans
#pragma unroll
        for (int ks = 0; ks < 4; ks++) {
            uint32_t vf[8][2];
            int kvrow = ks * 16 + (lane & 15);
            uint32_t rsw = kvrow * 128;
#pragma unroll
            for (int p = 0; p < 4; p++) {
                int dseg = 2 * p + (lane >> 4);
                uint32_t addr = stg + 16384 + rsw + ((dseg ^ (kvrow & 7)) << 4);
                ldsm4t(&vf[2 * p][0], addr);
            }
#pragma unroll
            for (int nt = 0; nt < 8; nt++) {
                mma16816(O[nt], aPh[ks], vf[nt]);
                mma16816(O[nt], aPl[ks], vf[nt]);
            }
#pragma unroll
            for (int p = 0; p < 4; p++) {
                int dseg = 2 * p + (lane >> 4);
                uint32_t addr = stg + 24576 + rsw + ((dseg ^ (kvrow & 7)) << 4);
                ldsm4t(&vf[2 * p][0], addr);
            }
#pragma unroll
            for (int nt = 0; nt < 8; nt++)
                mma16816(O[nt], aPh[ks], vf[nt]);
        }
    }

    // ---- normalize + write out[b][l][h*64+d]
    float i0 = 1.f / l0, i1 = 1.f / l1;
    size_t r0 = (size_t)(b * LL + qb + wm + gid);
#pragma unroll
    for (int nt = 0; nt < 8; nt++) {
        int d = h * HDIM + nt * 8 + 2 * tg;
        *(float2*)(out + r0 * DD + d) = make_float2(O[nt][0] * i0, O[nt][1] * i0);
        *(float2*)(out + (r0 + 8) * DD + d) = make_float2(O[nt][2] * i1, O[nt][3] * i1);
    }
}

// ---------------------------------------------------------------------------
extern "C" void kernel_launch(void* const* d_in, const int* in_sizes, int n_in,
                              void* d_out, int out_size)
{
    const float* x    = (const float*)d_in[0];
    const float* w_in = (const float*)d_in[1];
    const float* off  = (const float*)d_in[2];
    const float* amp  = (const float*)d_in[3];
    const float* shp  = (const float*)d_in[4];
    float* out = (float*)d_out;

    scores_kernel<<<HH, 256>>>(off, amp, shp);

    {
        __nv_bfloat16* abig;
        __nv_bfloat16* bbig;
        cudaGetSymbolAddress((void**)&abig, g_Abig);
        cudaGetSymbolAddress((void**)&bbig, g_Bbig);
        convert_kernel<<<(MTOT * DD / 4) / 256, 256>>>(x, abig);
        convert_kernel<<<(D3 * DD / 4) / 256, 256>>>(w_in, bbig);
    }

    {
        const int smem_bytes = 3 * STG_BYTES;  // 98304
        cudaFuncSetAttribute(proj_mma, cudaFuncAttributeMaxDynamicSharedMemorySize,
                             smem_bytes);
        dim3 grid(D3 / 128, MTOT / 128);
        proj_mma<<<grid, 256, smem_bytes>>>();
    }

    {
        const int smem_bytes = 65536 + 2 * 192 * 4;  // 67072
        cudaFuncSetAttribute(attn_mma, cudaFuncAttributeMaxDynamicSharedMemorySize,
                             smem_bytes);
        dim3 agrid(LL / 128, HH, BB);
        attn_mma<<<agrid, 256, smem_bytes>>>(out);
    }
}

// round 6
// speedup vs baseline: 2.9563x; 1.0719x over previous
#include <cuda_runtime.h>
#include <cuda_bf16.h>
#include <math.h>
#include <stdint.h>

#define BB 2
#define LL 2048
#define DD 1024
#define HH 16
#define HDIM 64
#define D3 3072
#define RLEN 4095   // 2*L - 1
#define MTOT 4096   // B*L
#define K2 2048     // hi|lo concatenated K

// Scratch (no allocation allowed)
__device__ float g_scores[HH * RLEN];
__device__ __align__(1024) __nv_bfloat16 g_Abig[(size_t)MTOT * K2];  // x  hi|lo
__device__ __align__(1024) __nv_bfloat16 g_Bbig[(size_t)D3 * K2];    // w  hi|lo
// Per-head bf16 hi/lo tensors: [b][h][l][64]
#define HSZ ((size_t)BB * HH * LL * HDIM)
__device__ __align__(1024) __nv_bfloat16 g_Qh[HSZ];
__device__ __align__(1024) __nv_bfloat16 g_Ql[HSZ];
__device__ __align__(1024) __nv_bfloat16 g_Kh[HSZ];
__device__ __align__(1024) __nv_bfloat16 g_Kl[HSZ];
__device__ __align__(1024) __nv_bfloat16 g_Vh[HSZ];
__device__ __align__(1024) __nv_bfloat16 g_Vl[HSZ];

__device__ __forceinline__ uint32_t smem_to_u32(const void* p) {
    uint32_t a;
    asm("{ .reg .u64 t; cvta.to.shared.u64 t, %1; cvt.u32.u64 %0, t; }"
        : "=r"(a) : "l"(p));
    return a;
}
#define CP16(dst, src) \
    asm volatile("cp.async.cg.shared.global [%0], [%1], 16;" :: "r"(dst), "l"(src))
#define CP_COMMIT() asm volatile("cp.async.commit_group;" ::: "memory")
#define CP_WAITG(n) asm volatile("cp.async.wait_group %0;" :: "n"(n) : "memory")

__device__ __forceinline__ void ldsm4(uint32_t* r, uint32_t addr) {
    asm volatile("ldmatrix.sync.aligned.m8n8.x4.shared.b16 {%0, %1, %2, %3}, [%4];"
                 : "=r"(r[0]), "=r"(r[1]), "=r"(r[2]), "=r"(r[3]) : "r"(addr));
}
__device__ __forceinline__ void ldsm4t(uint32_t* r, uint32_t addr) {
    asm volatile("ldmatrix.sync.aligned.m8n8.x4.trans.shared.b16 {%0, %1, %2, %3}, [%4];"
                 : "=r"(r[0]), "=r"(r[1]), "=r"(r[2]), "=r"(r[3]) : "r"(addr));
}
__device__ __forceinline__ void mma16816(float* c, const uint32_t* a, const uint32_t* b) {
    asm volatile("mma.sync.aligned.m16n8k16.row.col.f32.bf16.bf16.f32 "
                 "{%0, %1, %2, %3}, {%4, %5, %6, %7}, {%8, %9}, {%0, %1, %2, %3};"
                 : "+f"(c[0]), "+f"(c[1]), "+f"(c[2]), "+f"(c[3])
                 : "r"(a[0]), "r"(a[1]), "r"(a[2]), "r"(a[3]), "r"(b[0]), "r"(b[1]));
}
// packed bf16x2: low = lo, high = hi
__device__ __forceinline__ uint32_t packbf(float lo, float hi) {
    uint32_t r;
    asm("cvt.rn.bf16x2.f32 %0, %1, %2;" : "=r"(r) : "f"(hi), "f"(lo));
    return r;
}

// ---------------------------------------------------------------------------
// Kernel 1: TISA bias table (grid 16 x 8 for full-chip spread)
// ---------------------------------------------------------------------------
__global__ __launch_bounds__(256) void scores_kernel(const float* __restrict__ off,
                                                     const float* __restrict__ amp,
                                                     const float* __restrict__ shp)
{
    int h = blockIdx.x;
    __shared__ float so[16], sa[16], ss[16];
    if (threadIdx.x < 16) {
        so[threadIdx.x] = off[h * 16 + threadIdx.x];
        sa[threadIdx.x] = amp[h * 16 + threadIdx.x];
        ss[threadIdx.x] = fabsf(shp[h * 16 + threadIdx.x]);
    }
    __syncthreads();
    for (int r = blockIdx.y * 256 + threadIdx.x; r < RLEN; r += 8 * 256) {
        float rel = (float)(r - (LL - 1));
        float acc = 0.f;
#pragma unroll
        for (int k = 0; k < 16; k++) {
            float d = so[k] - rel;
            acc += sa[k] * expf(-ss[k] * d * d);
        }
        g_scores[h * RLEN + r] = acc;
    }
}

// ---------------------------------------------------------------------------
// Kernel 2a: fp32 -> bf16 hi/lo split for GEMM inputs
// ---------------------------------------------------------------------------
__global__ __launch_bounds__(256) void convert_kernel(const float* __restrict__ src,
                                                      __nv_bfloat16* __restrict__ dst)
{
    int idx = blockIdx.x * 256 + threadIdx.x;
    int row = idx >> 8;
    int k = (idx & 255) << 2;
    float4 v = *(const float4*)(src + (size_t)row * DD + k);
    __nv_bfloat16 h0 = __float2bfloat16_rn(v.x);
    __nv_bfloat16 h1 = __float2bfloat16_rn(v.y);
    __nv_bfloat16 h2 = __float2bfloat16_rn(v.z);
    __nv_bfloat16 h3 = __float2bfloat16_rn(v.w);
    __nv_bfloat16 l0 = __float2bfloat16_rn(v.x - __bfloat162float(h0));
    __nv_bfloat16 l1 = __float2bfloat16_rn(v.y - __bfloat162float(h1));
    __nv_bfloat16 l2 = __float2bfloat16_rn(v.z - __bfloat162float(h2));
    __nv_bfloat16 l3 = __float2bfloat16_rn(v.w - __bfloat162float(h3));
    __nv_bfloat162* dh = (__nv_bfloat162*)(dst + (size_t)row * K2 + k);
    dh[0] = __nv_bfloat162(h0, h1);
    dh[1] = __nv_bfloat162(h2, h3);
    __nv_bfloat162* dl = (__nv_bfloat162*)(dst + (size_t)row * K2 + DD + k);
    dl[0] = __nv_bfloat162(l0, l1);
    dl[1] = __nv_bfloat162(l2, l3);
}

// ---------------------------------------------------------------------------
// Kernel 2b: HMMA split GEMM, epilogue writes per-head bf16 hi/lo q,k,v.
// CTA 128x128, 8 warps (4M x 2N), warp tile 32x64, BK=64, 3-stage cp.async.
// __launch_bounds__(256,2): 2 CTAs/SM for latency hiding (16 warps).
// ---------------------------------------------------------------------------
#define NCHUNK 48
#define STG_BYTES 32768

__device__ __forceinline__ void load_chunk(uint32_t sA, uint32_t sB,
                                           const __nv_bfloat16* __restrict__ gA,
                                           const __nv_bfloat16* __restrict__ gB,
                                           int bm, int bn, int ka, int kb, int tid)
{
#pragma unroll
    for (int i = 0; i < 4; i++) {
        int s = tid + i * 256;
        int row = s >> 3, kseg = s & 7;
        uint32_t dst = sA + row * 128 + ((kseg ^ (row & 7)) << 4);
        const void* src = gA + (size_t)(bm + row) * K2 + ka + kseg * 8;
        CP16(dst, src);
    }
#pragma unroll
    for (int i = 0; i < 4; i++) {
        int s = tid + i * 256;
        int row = s >> 3, kseg = s & 7;
        uint32_t dst = sB + row * 128 + ((kseg ^ (row & 7)) << 4);
        const void* src = gB + (size_t)(bn + row) * K2 + kb + kseg * 8;
        CP16(dst, src);
    }
    CP_COMMIT();
}

__global__ __launch_bounds__(256, 2) void proj_mma()
{
    extern __shared__ char smem[];
    const uint32_t sbase = smem_to_u32(smem);
    const int tid = threadIdx.x;
    const int wid = tid >> 5, lane = tid & 31;
    const int bm = blockIdx.y * 128, bn = blockIdx.x * 128;
    const int wm = (wid >> 1) * 32;
    const int wn = (wid & 1) * 64;

    float acc[2][8][4];
#pragma unroll
    for (int mt = 0; mt < 2; mt++)
#pragma unroll
        for (int nt = 0; nt < 8; nt++)
#pragma unroll
            for (int c = 0; c < 4; c++) acc[mt][nt][c] = 0.f;

    auto kamap = [](int t, int& ka, int& kb) {
        int pass = t >> 4, kt = t & 15;
        ka = (pass == 2) ? (DD + kt * 64) : (kt * 64);
        kb = (pass == 1) ? (DD + kt * 64) : (kt * 64);
    };

    {
        int ka, kb;
        kamap(0, ka, kb);
        load_chunk(sbase, sbase + 16384, g_Abig, g_Bbig, bm, bn, ka, kb, tid);
        kamap(1, ka, kb);
        load_chunk(sbase + STG_BYTES, sbase + STG_BYTES + 16384, g_Abig, g_Bbig,
                   bm, bn, ka, kb, tid);
    }

    for (int t = 0; t < NCHUNK; t++) {
        CP_WAITG(1);
        __syncthreads();

        if (t + 2 < NCHUNK) {
            int ka, kb;
            kamap(t + 2, ka, kb);
            uint32_t s = sbase + ((t + 2) % 3) * STG_BYTES;
            load_chunk(s, s + 16384, g_Abig, g_Bbig, bm, bn, ka, kb, tid);
        } else {
            CP_COMMIT();
        }

        const uint32_t sA = sbase + (t % 3) * STG_BYTES;
        const uint32_t sB = sA + 16384;

#pragma unroll
        for (int kk = 0; kk < 4; kk++) {
            uint32_t a[2][4];
#pragma unroll
            for (int mt = 0; mt < 2; mt++) {
                int row = wm + mt * 16 + (lane & 15);
                int kseg = kk * 2 + (lane >> 4);
                uint32_t addr = sA + row * 128 + ((kseg ^ (row & 7)) << 4);
                ldsm4(a[mt], addr);
            }
            uint32_t b[8][2];
#pragma unroll
            for (int p = 0; p < 4; p++) {
                int row = wn + p * 16 + (lane & 7) + ((lane >> 4) << 3);
                int kseg = kk * 2 + ((lane >> 3) & 1);
                uint32_t addr = sB + row * 128 + ((kseg ^ (row & 7)) << 4);
                ldsm4(&b[2 * p][0], addr);
            }
#pragma unroll
            for (int mt = 0; mt < 2; mt++)
#pragma unroll
                for (int nt = 0; nt < 8; nt++)
                    mma16816(acc[mt][nt], a[mt], b[nt]);
        }
        __syncthreads();
    }

    // Epilogue: split each value into bf16 hi/lo, write to per-head q/k/v arrays.
#pragma unroll
    for (int mt = 0; mt < 2; mt++) {
        int row0 = bm + wm + mt * 16 + (lane >> 2);
        int b = row0 >> 11;
        int l = row0 & 2047;
#pragma unroll
        for (int nt = 0; nt < 8; nt++) {
            int col = bn + wn + nt * 8 + (lane & 3) * 2;
            int ty = col >> 10;            // 0=k, 1=v, 2=q
            int h = (col >> 6) & 15;
            int d = col & 63;
            float sc = (ty == 2) ? 0.125f : 1.0f;
            float v0 = acc[mt][nt][0] * sc, v1 = acc[mt][nt][1] * sc;
            float v2 = acc[mt][nt][2] * sc, v3 = acc[mt][nt][3] * sc;
            uint32_t h01 = packbf(v0, v1), h23 = packbf(v2, v3);
            uint32_t l01 = packbf(v0 - __uint_as_float(h01 << 16),
                                  v1 - __uint_as_float(h01 & 0xFFFF0000u));
            uint32_t l23 = packbf(v2 - __uint_as_float(h23 << 16),
                                  v3 - __uint_as_float(h23 & 0xFFFF0000u));
            __nv_bfloat16 *dh, *dl;
            if (ty == 0)      { dh = g_Kh; dl = g_Kl; }
            else if (ty == 1) { dh = g_Vh; dl = g_Vl; }
            else              { dh = g_Qh; dl = g_Ql; }
            size_t base0 = ((size_t)(b * HH + h) * LL + l) * HDIM + d;
            size_t base1 = base0 + 8 * HDIM;
            *(uint32_t*)(dh + base0) = h01;
            *(uint32_t*)(dl + base0) = l01;
            *(uint32_t*)(dh + base1) = h23;
            *(uint32_t*)(dl + base1) = l23;
        }
    }
}

// ---------------------------------------------------------------------------
// Kernel 3: HMMA flash attention, hi/lo split, split K/V commit groups so the
// V load hides under QK + softmax. Q staged in stage-1 smem (free until t=1).
// smem: stage s at s*32768: Khi|Klo|Vhi|Vlo (8KB each). bias sb[2][192] @65536.
// ---------------------------------------------------------------------------
__device__ __forceinline__ void attn_load_k(uint32_t sbase, int stage, int bh,
                                            int kb, int tid)
{
    uint32_t stg = sbase + stage * 32768;
#pragma unroll
    for (int i = 0; i < 4; i++) {
        const int comp = i >> 1;           // 0=Khi 1=Klo
        int row = (tid >> 3) + 32 * (i & 1);
        int kseg = tid & 7;
        const __nv_bfloat16* gb = comp ? g_Kl : g_Kh;
        uint32_t dst = stg + comp * 8192 + row * 128 + ((kseg ^ (row & 7)) << 4);
        const void* src = gb + ((size_t)bh * LL + kb + row) * HDIM + kseg * 8;
        CP16(dst, src);
    }
    CP_COMMIT();
}
__device__ __forceinline__ void attn_load_v(uint32_t sbase, int stage, int bh,
                                            int kb, int tid)
{
    uint32_t stg = sbase + stage * 32768 + 16384;
#pragma unroll
    for (int i = 0; i < 4; i++) {
        const int comp = i >> 1;           // 0=Vhi 1=Vlo
        int row = (tid >> 3) + 32 * (i & 1);
        int kseg = tid & 7;
        const __nv_bfloat16* gb = comp ? g_Vl : g_Vh;
        uint32_t dst = stg + comp * 8192 + row * 128 + ((kseg ^ (row & 7)) << 4);
        const void* src = gb + ((size_t)bh * LL + kb + row) * HDIM + kseg * 8;
        CP16(dst, src);
    }
    CP_COMMIT();
}

__global__ __launch_bounds__(256) void attn_mma(float* __restrict__ out)
{
    extern __shared__ char smem[];
    const uint32_t sbase = smem_to_u32(smem);
    float* sb = (float*)(smem + 65536);   // [2][192]
    const int tid = threadIdx.x;
    const int wid = tid >> 5, lane = tid & 31;
    const int gid = lane >> 2, tg = lane & 3;
    const int qb = blockIdx.x * 128;
    const int h = blockIdx.y, b = blockIdx.z;
    const int bh = b * HH + h;
    const int wm = wid * 16;
    const float* srow = g_scores + h * RLEN;

    // --- Prologue: Q (hi/lo) into stage-1 smem; K0/V0 issued right behind.
#pragma unroll
    for (int i = 0; i < 8; i++) {
        const int comp = i >> 2;
        int row = (tid >> 3) + 32 * (i & 3);
        int kseg = tid & 7;
        const __nv_bfloat16* gb = comp ? g_Ql : g_Qh;
        uint32_t dst = sbase + 32768 + comp * 16384 + row * 128 +
                       ((kseg ^ (row & 7)) << 4);
        const void* src = gb + ((size_t)bh * LL + qb + row) * HDIM + kseg * 8;
        CP16(dst, src);
    }
    CP_COMMIT();                         // group: Q
    attn_load_k(sbase, 0, bh, 0, tid);   // group: K0
    attn_load_v(sbase, 0, bh, 0, tid);   // group: V0
    if (tid < 192) {
        int sidx = qb + 1984 + tid;
        sb[tid] = srow[min(sidx, RLEN - 1)];
    }
    CP_WAITG(2);                         // Q done (K0/V0 may be pending)
    __syncthreads();

    uint32_t aQh[4][4], aQl[4][4];
#pragma unroll
    for (int ks = 0; ks < 4; ks++) {
        int row = wm + (lane & 15);
        int kseg = ks * 2 + (lane >> 4);
        uint32_t sw = row * 128 + ((kseg ^ (row & 7)) << 4);
        ldsm4(aQh[ks], sbase + 32768 + sw);
        ldsm4(aQl[ks], sbase + 49152 + sw);
    }
    __syncthreads();   // Q consumed; stage 1 may now be overwritten

    float O[8][4];
#pragma unroll
    for (int nt = 0; nt < 8; nt++)
#pragma unroll
        for (int c = 0; c < 4; c++) O[nt][c] = 0.f;
    float m0 = -1e30f, m1 = -1e30f, l0 = 0.f, l1 = 0.f;

    for (int t = 0; t < LL / 64; t++) {
        // pending here: K(t), V(t). Wait K only.
        CP_WAITG(1);
        __syncthreads();
        const uint32_t stg = sbase + (t & 1) * 32768;
        const float* sbt = sb + (t & 1) * 192;

        if (t + 1 < LL / 64) {
            attn_load_k(sbase, (t + 1) & 1, bh, (t + 1) * 64, tid);
            attn_load_v(sbase, (t + 1) & 1, bh, (t + 1) * 64, tid);
            if (tid < 192) {
                int sidx = qb - (t + 1) * 64 + 1984 + tid;
                sb[((t + 1) & 1) * 192 + tid] = srow[min(sidx, RLEN - 1)];
            }
        } else {
            CP_COMMIT();
            CP_COMMIT();
        }

        // ---- S = Q K^T (3-pass split), fp32 accum
        float S[8][4];
#pragma unroll
        for (int nt = 0; nt < 8; nt++)
#pragma unroll
            for (int c = 0; c < 4; c++) S[nt][c] = 0.f;

#pragma unroll
        for (int kk = 0; kk < 4; kk++) {
            uint32_t kf[8][2];
            int krow = (lane & 7) + ((lane >> 4) << 3);
            int kkseg = kk * 2 + ((lane >> 3) & 1);
#pragma unroll
            for (int p = 0; p < 4; p++) {
                int row = krow + p * 16;
                uint32_t addr = stg + row * 128 + ((kkseg ^ (row & 7)) << 4);
                ldsm4(&kf[2 * p][0], addr);
            }
#pragma unroll
            for (int nt = 0; nt < 8; nt++) {
                mma16816(S[nt], aQh[kk], kf[nt]);
                mma16816(S[nt], aQl[kk], kf[nt]);
            }
#pragma unroll
            for (int p = 0; p < 4; p++) {
                int row = krow + p * 16;
                uint32_t addr = stg + 8192 + row * 128 + ((kkseg ^ (row & 7)) << 4);
                ldsm4(&kf[2 * p][0], addr);
            }
#pragma unroll
            for (int nt = 0; nt < 8; nt++)
                mma16816(S[nt], aQh[kk], kf[nt]);
        }

        // ---- bias + online softmax (V load still in flight underneath)
        const int jbase = wm + gid + 63 - 2 * tg;
        float mx0 = -1e30f, mx1 = -1e30f;
#pragma unroll
        for (int nt = 0; nt < 8; nt++) {
            int j = jbase - 8 * nt;
            S[nt][0] += sbt[j];
            S[nt][1] += sbt[j - 1];
            S[nt][2] += sbt[j + 8];
            S[nt][3] += sbt[j + 7];
            mx0 = fmaxf(mx0, fmaxf(S[nt][0], S[nt][1]));
            mx1 = fmaxf(mx1, fmaxf(S[nt][2], S[nt][3]));
        }
        mx0 = fmaxf(mx0, __shfl_xor_sync(0xffffffffu, mx0, 1));
        mx0 = fmaxf(mx0, __shfl_xor_sync(0xffffffffu, mx0, 2));
        mx1 = fmaxf(mx1, __shfl_xor_sync(0xffffffffu, mx1, 1));
        mx1 = fmaxf(mx1, __shfl_xor_sync(0xffffffffu, mx1, 2));
        float nm0 = fmaxf(m0, mx0), nm1 = fmaxf(m1, mx1);
        float c0 = __expf(m0 - nm0), c1 = __expf(m1 - nm1);
        m0 = nm0; m1 = nm1;

        float rs0 = 0.f, rs1 = 0.f;
        uint32_t aPh[4][4], aPl[4][4];
#pragma unroll
        for (int nt = 0; nt < 8; nt++) {
            float p0 = __expf(S[nt][0] - nm0);
            float p1 = __expf(S[nt][1] - nm0);
            float p2 = __expf(S[nt][2] - nm1);
            float p3 = __expf(S[nt][3] - nm1);
            rs0 += p0 + p1;
            rs1 += p2 + p3;
            uint32_t h01 = packbf(p0, p1), h23 = packbf(p2, p3);
            uint32_t l01 = packbf(p0 - __uint_as_float(h01 << 16),
                                  p1 - __uint_as_float(h01 & 0xFFFF0000u));
            uint32_t l23 = packbf(p2 - __uint_as_float(h23 << 16),
                                  p3 - __uint_as_float(h23 & 0xFFFF0000u));
            int ks = nt >> 1, hf = (nt & 1) * 2;
            aPh[ks][hf] = h01; aPh[ks][hf + 1] = h23;
            aPl[ks][hf] = l01; aPl[ks][hf + 1] = l23;
        }
        rs0 += __shfl_xor_sync(0xffffffffu, rs0, 1);
        rs0 += __shfl_xor_sync(0xffffffffu, rs0, 2);
        rs1 += __shfl_xor_sync(0xffffffffu, rs1, 1);
        rs1 += __shfl_xor_sync(0xffffffffu, rs1, 2);
        l0 = l0 * c0 + rs0;
        l1 = l1 * c1 + rs1;
#pragma unroll
        for (int nt = 0; nt < 8; nt++) {
            O[nt][0] *= c0; O[nt][1] *= c0;
            O[nt][2] *= c1; O[nt][3] *= c1;
        }

        // pending: V(t), K(t+1), V(t+1). Wait V(t).
        CP_WAITG(2);
        __syncthreads();

        // ---- O += P V (3-pass split), V frags via ldmatrix.trans
#pragma unroll
        for (int ks = 0; ks < 4; ks++) {
            uint32_t vf[8][2];
            int kvrow = ks * 16 + (lane & 15);
            uint32_t rsw = kvrow * 128;
#pragma unroll
            for (int p = 0; p < 4; p++) {
                int dseg = 2 * p + (lane >> 4);
                uint32_t addr = stg + 16384 + rsw + ((dseg ^ (kvrow & 7)) << 4);
                ldsm4t(&vf[2 * p][0], addr);
            }
#pragma unroll
            for (int nt = 0; nt < 8; nt++) {
                mma16816(O[nt], aPh[ks], vf[nt]);
                mma16816(O[nt], aPl[ks], vf[nt]);
            }
#pragma unroll
            for (int p = 0; p < 4; p++) {
                int dseg = 2 * p + (lane >> 4);
                uint32_t addr = stg + 24576 + rsw + ((dseg ^ (kvrow & 7)) << 4);
                ldsm4t(&vf[2 * p][0], addr);
            }
#pragma unroll
            for (int nt = 0; nt < 8; nt++)
                mma16816(O[nt], aPh[ks], vf[nt]);
        }
    }

    // ---- normalize + write out[b][l][h*64+d]
    float i0 = 1.f / l0, i1 = 1.f / l1;
    size_t r0 = (size_t)(b * LL + qb + wm + gid);
#pragma unroll
    for (int nt = 0; nt < 8; nt++) {
        int d = h * HDIM + nt * 8 + 2 * tg;
        *(float2*)(out + r0 * DD + d) = make_float2(O[nt][0] * i0, O[nt][1] * i0);
        *(float2*)(out + (r0 + 8) * DD + d) = make_float2(O[nt][2] * i1, O[nt][3] * i1);
    }
}

// ---------------------------------------------------------------------------
extern "C" void kernel_launch(void* const* d_in, const int* in_sizes, int n_in,
                              void* d_out, int out_size)
{
    const float* x    = (const float*)d_in[0];
    const float* w_in = (const float*)d_in[1];
    const float* off  = (const float*)d_in[2];
    const float* amp  = (const float*)d_in[3];
    const float* shp  = (const float*)d_in[4];
    float* out = (float*)d_out;

    scores_kernel<<<dim3(HH, 8), 256>>>(off, amp, shp);

    {
        __nv_bfloat16* abig;
        __nv_bfloat16* bbig;
        cudaGetSymbolAddress((void**)&abig, g_Abig);
        cudaGetSymbolAddress((void**)&bbig, g_Bbig);
        convert_kernel<<<(MTOT * DD / 4) / 256, 256>>>(x, abig);
        convert_kernel<<<(D3 * DD / 4) / 256, 256>>>(w_in, bbig);
    }

    {
        const int smem_bytes = 3 * STG_BYTES;  // 98304
        cudaFuncSetAttribute(proj_mma, cudaFuncAttributeMaxDynamicSharedMemorySize,
                             smem_bytes);
        dim3 grid(D3 / 128, MTOT / 128);
        proj_mma<<<grid, 256, smem_bytes>>>();
    }

    {
        const int smem_bytes = 65536 + 2 * 192 * 4;  // 67072
        cudaFuncSetAttribute(attn_mma, cudaFuncAttributeMaxDynamicSharedMemorySize,
                             smem_bytes);
        dim3 agrid(LL / 128, HH, BB);
        attn_mma<<<agrid, 256, smem_bytes>>>(out);
    }
}

// round 7
// speedup vs baseline: 3.0711x; 1.0388x over previous
#include <cuda_runtime.h>
#include <cuda_bf16.h>
#include <math.h>
#include <stdint.h>

#define BB 2
#define LL 2048
#define DD 1024
#define HH 16
#define HDIM 64
#define D3 3072
#define RLEN 4095   // 2*L - 1
#define MTOT 4096   // B*L
#define K2 2048     // hi|lo concatenated K

// Scratch (no allocation allowed)
__device__ float g_scores[HH * RLEN];
__device__ __align__(1024) __nv_bfloat16 g_Abig[(size_t)MTOT * K2];  // x  hi|lo
__device__ __align__(1024) __nv_bfloat16 g_Bbig[(size_t)D3 * K2];    // w  hi|lo
// Per-head bf16 hi/lo tensors: [b][h][l][64]
#define HSZ ((size_t)BB * HH * LL * HDIM)
__device__ __align__(1024) __nv_bfloat16 g_Qh[HSZ];
__device__ __align__(1024) __nv_bfloat16 g_Ql[HSZ];
__device__ __align__(1024) __nv_bfloat16 g_Kh[HSZ];
__device__ __align__(1024) __nv_bfloat16 g_Kl[HSZ];
__device__ __align__(1024) __nv_bfloat16 g_Vh[HSZ];
__device__ __align__(1024) __nv_bfloat16 g_Vl[HSZ];

__device__ __forceinline__ uint32_t smem_to_u32(const void* p) {
    uint32_t a;
    asm("{ .reg .u64 t; cvta.to.shared.u64 t, %1; cvt.u32.u64 %0, t; }"
        : "=r"(a) : "l"(p));
    return a;
}
#define CP16(dst, src) \
    asm volatile("cp.async.cg.shared.global [%0], [%1], 16;" :: "r"(dst), "l"(src))
#define CP_COMMIT() asm volatile("cp.async.commit_group;" ::: "memory")
#define CP_WAITG(n) asm volatile("cp.async.wait_group %0;" :: "n"(n) : "memory")

__device__ __forceinline__ void ldsm4(uint32_t* r, uint32_t addr) {
    asm volatile("ldmatrix.sync.aligned.m8n8.x4.shared.b16 {%0, %1, %2, %3}, [%4];"
                 : "=r"(r[0]), "=r"(r[1]), "=r"(r[2]), "=r"(r[3]) : "r"(addr));
}
__device__ __forceinline__ void ldsm4t(uint32_t* r, uint32_t addr) {
    asm volatile("ldmatrix.sync.aligned.m8n8.x4.trans.shared.b16 {%0, %1, %2, %3}, [%4];"
                 : "=r"(r[0]), "=r"(r[1]), "=r"(r[2]), "=r"(r[3]) : "r"(addr));
}
__device__ __forceinline__ void mma16816(float* c, const uint32_t* a, const uint32_t* b) {
    asm volatile("mma.sync.aligned.m16n8k16.row.col.f32.bf16.bf16.f32 "
                 "{%0, %1, %2, %3}, {%4, %5, %6, %7}, {%8, %9}, {%0, %1, %2, %3};"
                 : "+f"(c[0]), "+f"(c[1]), "+f"(c[2]), "+f"(c[3])
                 : "r"(a[0]), "r"(a[1]), "r"(a[2]), "r"(a[3]), "r"(b[0]), "r"(b[1]));
}
// packed bf16x2: low = lo, high = hi
__device__ __forceinline__ uint32_t packbf(float lo, float hi) {
    uint32_t r;
    asm("cvt.rn.bf16x2.f32 %0, %1, %2;" : "=r"(r) : "f"(hi), "f"(lo));
    return r;
}

// ---------------------------------------------------------------------------
// Kernel 1: TISA bias table (grid 16 x 8 for full-chip spread)
// ---------------------------------------------------------------------------
__global__ __launch_bounds__(256) void scores_kernel(const float* __restrict__ off,
                                                     const float* __restrict__ amp,
                                                     const float* __restrict__ shp)
{
    int h = blockIdx.x;
    __shared__ float so[16], sa[16], ss[16];
    if (threadIdx.x < 16) {
        so[threadIdx.x] = off[h * 16 + threadIdx.x];
        sa[threadIdx.x] = amp[h * 16 + threadIdx.x];
        ss[threadIdx.x] = fabsf(shp[h * 16 + threadIdx.x]);
    }
    __syncthreads();
    for (int r = blockIdx.y * 256 + threadIdx.x; r < RLEN; r += 8 * 256) {
        float rel = (float)(r - (LL - 1));
        float acc = 0.f;
#pragma unroll
        for (int k = 0; k < 16; k++) {
            float d = so[k] - rel;
            acc += sa[k] * expf(-ss[k] * d * d);
        }
        g_scores[h * RLEN + r] = acc;
    }
}

// ---------------------------------------------------------------------------
// Kernel 2a: fp32 -> bf16 hi/lo split for GEMM inputs
// ---------------------------------------------------------------------------
__global__ __launch_bounds__(256) void convert_kernel(const float* __restrict__ src,
                                                      __nv_bfloat16* __restrict__ dst)
{
    int idx = blockIdx.x * 256 + threadIdx.x;
    int row = idx >> 8;
    int k = (idx & 255) << 2;
    float4 v = *(const float4*)(src + (size_t)row * DD + k);
    __nv_bfloat16 h0 = __float2bfloat16_rn(v.x);
    __nv_bfloat16 h1 = __float2bfloat16_rn(v.y);
    __nv_bfloat16 h2 = __float2bfloat16_rn(v.z);
    __nv_bfloat16 h3 = __float2bfloat16_rn(v.w);
    __nv_bfloat16 l0 = __float2bfloat16_rn(v.x - __bfloat162float(h0));
    __nv_bfloat16 l1 = __float2bfloat16_rn(v.y - __bfloat162float(h1));
    __nv_bfloat16 l2 = __float2bfloat16_rn(v.z - __bfloat162float(h2));
    __nv_bfloat16 l3 = __float2bfloat16_rn(v.w - __bfloat162float(h3));
    __nv_bfloat162* dh = (__nv_bfloat162*)(dst + (size_t)row * K2 + k);
    dh[0] = __nv_bfloat162(h0, h1);
    dh[1] = __nv_bfloat162(h2, h3);
    __nv_bfloat162* dl = (__nv_bfloat162*)(dst + (size_t)row * K2 + DD + k);
    dl[0] = __nv_bfloat162(l0, l1);
    dl[1] = __nv_bfloat162(l2, l3);
}

// ---------------------------------------------------------------------------
// Kernel 2b: HMMA split GEMM, epilogue writes per-head bf16 hi/lo q,k,v.
// CTA 128x128, 8 warps (4M x 2N), warp tile 32x64, BK=64, 3-stage cp.async.
// __launch_bounds__(256,2): 2 CTAs/SM for latency hiding (16 warps).
// ---------------------------------------------------------------------------
#define NCHUNK 48
#define STG_BYTES 32768

__device__ __forceinline__ void load_chunk(uint32_t sA, uint32_t sB,
                                           const __nv_bfloat16* __restrict__ gA,
                                           const __nv_bfloat16* __restrict__ gB,
                                           int bm, int bn, int ka, int kb, int tid)
{
#pragma unroll
    for (int i = 0; i < 4; i++) {
        int s = tid + i * 256;
        int row = s >> 3, kseg = s & 7;
        uint32_t dst = sA + row * 128 + ((kseg ^ (row & 7)) << 4);
        const void* src = gA + (size_t)(bm + row) * K2 + ka + kseg * 8;
        CP16(dst, src);
    }
#pragma unroll
    for (int i = 0; i < 4; i++) {
        int s = tid + i * 256;
        int row = s >> 3, kseg = s & 7;
        uint32_t dst = sB + row * 128 + ((kseg ^ (row & 7)) << 4);
        const void* src = gB + (size_t)(bn + row) * K2 + kb + kseg * 8;
        CP16(dst, src);
    }
    CP_COMMIT();
}

__global__ __launch_bounds__(256, 2) void proj_mma()
{
    extern __shared__ char smem[];
    const uint32_t sbase = smem_to_u32(smem);
    const int tid = threadIdx.x;
    const int wid = tid >> 5, lane = tid & 31;
    const int bm = blockIdx.y * 128, bn = blockIdx.x * 128;
    const int wm = (wid >> 1) * 32;
    const int wn = (wid & 1) * 64;

    float acc[2][8][4];
#pragma unroll
    for (int mt = 0; mt < 2; mt++)
#pragma unroll
        for (int nt = 0; nt < 8; nt++)
#pragma unroll
            for (int c = 0; c < 4; c++) acc[mt][nt][c] = 0.f;

    auto kamap = [](int t, int& ka, int& kb) {
        int pass = t >> 4, kt = t & 15;
        ka = (pass == 2) ? (DD + kt * 64) : (kt * 64);
        kb = (pass == 1) ? (DD + kt * 64) : (kt * 64);
    };

    {
        int ka, kb;
        kamap(0, ka, kb);
        load_chunk(sbase, sbase + 16384, g_Abig, g_Bbig, bm, bn, ka, kb, tid);
        kamap(1, ka, kb);
        load_chunk(sbase + STG_BYTES, sbase + STG_BYTES + 16384, g_Abig, g_Bbig,
                   bm, bn, ka, kb, tid);
    }

    for (int t = 0; t < NCHUNK; t++) {
        CP_WAITG(1);
        __syncthreads();

        if (t + 2 < NCHUNK) {
            int ka, kb;
            kamap(t + 2, ka, kb);
            uint32_t s = sbase + ((t + 2) % 3) * STG_BYTES;
            load_chunk(s, s + 16384, g_Abig, g_Bbig, bm, bn, ka, kb, tid);
        } else {
            CP_COMMIT();
        }

        const uint32_t sA = sbase + (t % 3) * STG_BYTES;
        const uint32_t sB = sA + 16384;

#pragma unroll
        for (int kk = 0; kk < 4; kk++) {
            uint32_t a[2][4];
#pragma unroll
            for (int mt = 0; mt < 2; mt++) {
                int row = wm + mt * 16 + (lane & 15);
                int kseg = kk * 2 + (lane >> 4);
                uint32_t addr = sA + row * 128 + ((kseg ^ (row & 7)) << 4);
                ldsm4(a[mt], addr);
            }
            uint32_t b[8][2];
#pragma unroll
            for (int p = 0; p < 4; p++) {
                int row = wn + p * 16 + (lane & 7) + ((lane >> 4) << 3);
                int kseg = kk * 2 + ((lane >> 3) & 1);
                uint32_t addr = sB + row * 128 + ((kseg ^ (row & 7)) << 4);
                ldsm4(&b[2 * p][0], addr);
            }
#pragma unroll
            for (int mt = 0; mt < 2; mt++)
#pragma unroll
                for (int nt = 0; nt < 8; nt++)
                    mma16816(acc[mt][nt], a[mt], b[nt]);
        }
        __syncthreads();
    }

    // Epilogue: split each value into bf16 hi/lo, write to per-head q/k/v arrays.
#pragma unroll
    for (int mt = 0; mt < 2; mt++) {
        int row0 = bm + wm + mt * 16 + (lane >> 2);
        int b = row0 >> 11;
        int l = row0 & 2047;
#pragma unroll
        for (int nt = 0; nt < 8; nt++) {
            int col = bn + wn + nt * 8 + (lane & 3) * 2;
            int ty = col >> 10;            // 0=k, 1=v, 2=q
            int h = (col >> 6) & 15;
            int d = col & 63;
            float sc = (ty == 2) ? 0.125f : 1.0f;
            float v0 = acc[mt][nt][0] * sc, v1 = acc[mt][nt][1] * sc;
            float v2 = acc[mt][nt][2] * sc, v3 = acc[mt][nt][3] * sc;
            uint32_t h01 = packbf(v0, v1), h23 = packbf(v2, v3);
            uint32_t l01 = packbf(v0 - __uint_as_float(h01 << 16),
                                  v1 - __uint_as_float(h01 & 0xFFFF0000u));
            uint32_t l23 = packbf(v2 - __uint_as_float(h23 << 16),
                                  v3 - __uint_as_float(h23 & 0xFFFF0000u));
            __nv_bfloat16 *dh, *dl;
            if (ty == 0)      { dh = g_Kh; dl = g_Kl; }
            else if (ty == 1) { dh = g_Vh; dl = g_Vl; }
            else              { dh = g_Qh; dl = g_Ql; }
            size_t base0 = ((size_t)(b * HH + h) * LL + l) * HDIM + d;
            size_t base1 = base0 + 8 * HDIM;
            *(uint32_t*)(dh + base0) = h01;
            *(uint32_t*)(dl + base0) = l01;
            *(uint32_t*)(dh + base1) = h23;
            *(uint32_t*)(dl + base1) = l23;
        }
    }
}

// ---------------------------------------------------------------------------
// Kernel 3: HMMA flash attention, hi/lo split, 2 CTAs/SM.
// smem: KV stage s at s*32768 (Khi|Klo|Vhi|Vlo, 8KB each);
//       Q dedicated @65536 (hi 16KB, lo 16KB); bias sb[2][192] @98304.
// Q-hi fragments live in registers; Q-lo reloaded via ldmatrix per k-step
// (single use per step) to fit the 128-reg budget for 2 CTAs/SM.
// ---------------------------------------------------------------------------
__device__ __forceinline__ void attn_load_k(uint32_t sbase, int stage, int bh,
                                            int kb, int tid)
{
    uint32_t stg = sbase + stage * 32768;
#pragma unroll
    for (int i = 0; i < 4; i++) {
        const int comp = i >> 1;           // 0=Khi 1=Klo
        int row = (tid >> 3) + 32 * (i & 1);
        int kseg = tid & 7;
        const __nv_bfloat16* gb = comp ? g_Kl : g_Kh;
        uint32_t dst = stg + comp * 8192 + row * 128 + ((kseg ^ (row & 7)) << 4);
        const void* src = gb + ((size_t)bh * LL + kb + row) * HDIM + kseg * 8;
        CP16(dst, src);
    }
    CP_COMMIT();
}
__device__ __forceinline__ void attn_load_v(uint32_t sbase, int stage, int bh,
                                            int kb, int tid)
{
    uint32_t stg = sbase + stage * 32768 + 16384;
#pragma unroll
    for (int i = 0; i < 4; i++) {
        const int comp = i >> 1;           // 0=Vhi 1=Vlo
        int row = (tid >> 3) + 32 * (i & 1);
        int kseg = tid & 7;
        const __nv_bfloat16* gb = comp ? g_Vl : g_Vh;
        uint32_t dst = stg + comp * 8192 + row * 128 + ((kseg ^ (row & 7)) << 4);
        const void* src = gb + ((size_t)bh * LL + kb + row) * HDIM + kseg * 8;
        CP16(dst, src);
    }
    CP_COMMIT();
}

__global__ __launch_bounds__(256, 2) void attn_mma(float* __restrict__ out)
{
    extern __shared__ char smem[];
    const uint32_t sbase = smem_to_u32(smem);
    const uint32_t sQ = sbase + 65536;     // Q hi @ +0, Q lo @ +16384
    float* sb = (float*)(smem + 98304);    // [2][192]
    const int tid = threadIdx.x;
    const int wid = tid >> 5, lane = tid & 31;
    const int gid = lane >> 2, tg = lane & 3;
    const int qb = blockIdx.x * 128;
    const int h = blockIdx.y, b = blockIdx.z;
    const int bh = b * HH + h;
    const int wm = wid * 16;
    const float* srow = g_scores + h * RLEN;

    // --- Prologue: Q (hi/lo) into dedicated smem; K0/V0 issued right behind.
#pragma unroll
    for (int i = 0; i < 8; i++) {
        const int comp = i >> 2;
        int row = (tid >> 3) + 32 * (i & 3);
        int kseg = tid & 7;
        const __nv_bfloat16* gb = comp ? g_Ql : g_Qh;
        uint32_t dst = sQ + comp * 16384 + row * 128 + ((kseg ^ (row & 7)) << 4);
        const void* src = gb + ((size_t)bh * LL + qb + row) * HDIM + kseg * 8;
        CP16(dst, src);
    }
    CP_COMMIT();                         // group: Q
    attn_load_k(sbase, 0, bh, 0, tid);   // group: K0
    attn_load_v(sbase, 0, bh, 0, tid);   // group: V0
    if (tid < 192) {
        int sidx = qb + 1984 + tid;
        sb[tid] = srow[min(sidx, RLEN - 1)];
    }
    CP_WAITG(2);                         // Q done (K0/V0 may be pending)
    __syncthreads();

    uint32_t aQh[4][4];
#pragma unroll
    for (int ks = 0; ks < 4; ks++) {
        int row = wm + (lane & 15);
        int kseg = ks * 2 + (lane >> 4);
        ldsm4(aQh[ks], sQ + row * 128 + ((kseg ^ (row & 7)) << 4));
    }

    float O[8][4];
#pragma unroll
    for (int nt = 0; nt < 8; nt++)
#pragma unroll
        for (int c = 0; c < 4; c++) O[nt][c] = 0.f;
    float m0 = -1e30f, m1 = -1e30f, l0 = 0.f, l1 = 0.f;

    for (int t = 0; t < LL / 64; t++) {
        // pending here: K(t), V(t). Wait K only.
        CP_WAITG(1);
        __syncthreads();
        const uint32_t stg = sbase + (t & 1) * 32768;
        const float* sbt = sb + (t & 1) * 192;

        if (t + 1 < LL / 64) {
            attn_load_k(sbase, (t + 1) & 1, bh, (t + 1) * 64, tid);
            attn_load_v(sbase, (t + 1) & 1, bh, (t + 1) * 64, tid);
            if (tid < 192) {
                int sidx = qb - (t + 1) * 64 + 1984 + tid;
                sb[((t + 1) & 1) * 192 + tid] = srow[min(sidx, RLEN - 1)];
            }
        } else {
            CP_COMMIT();
            CP_COMMIT();
        }

        // ---- S = Q K^T (3-pass split), fp32 accum
        float S[8][4];
#pragma unroll
        for (int nt = 0; nt < 8; nt++)
#pragma unroll
            for (int c = 0; c < 4; c++) S[nt][c] = 0.f;

#pragma unroll
        for (int kk = 0; kk < 4; kk++) {
            // Q-lo fragment for this k-step (from dedicated smem)
            uint32_t aQl[4];
            {
                int row = wm + (lane & 15);
                int kseg = kk * 2 + (lane >> 4);
                ldsm4(aQl, sQ + 16384 + row * 128 + ((kseg ^ (row & 7)) << 4));
            }
            uint32_t kf[8][2];
            int krow = (lane & 7) + ((lane >> 4) << 3);
            int kkseg = kk * 2 + ((lane >> 3) & 1);
#pragma unroll
            for (int p = 0; p < 4; p++) {
                int row = krow + p * 16;
                uint32_t addr = stg + row * 128 + ((kkseg ^ (row & 7)) << 4);
                ldsm4(&kf[2 * p][0], addr);
            }
#pragma unroll
            for (int nt = 0; nt < 8; nt++) {
                mma16816(S[nt], aQh[kk], kf[nt]);
                mma16816(S[nt], aQl, kf[nt]);
            }
#pragma unroll
            for (int p = 0; p < 4; p++) {
                int row = krow + p * 16;
                uint32_t addr = stg + 8192 + row * 128 + ((kkseg ^ (row & 7)) << 4);
                ldsm4(&kf[2 * p][0], addr);
            }
#pragma unroll
            for (int nt = 0; nt < 8; nt++)
                mma16816(S[nt], aQh[kk], kf[nt]);
        }

        // ---- bias + online softmax (V load still in flight underneath)
        const int jbase = wm + gid + 63 - 2 * tg;
        float mx0 = -1e30f, mx1 = -1e30f;
#pragma unroll
        for (int nt = 0; nt < 8; nt++) {
            int j = jbase - 8 * nt;
            S[nt][0] += sbt[j];
            S[nt][1] += sbt[j - 1];
            S[nt][2] += sbt[j + 8];
            S[nt][3] += sbt[j + 7];
            mx0 = fmaxf(mx0, fmaxf(S[nt][0], S[nt][1]));
            mx1 = fmaxf(mx1, fmaxf(S[nt][2], S[nt][3]));
        }
        mx0 = fmaxf(mx0, __shfl_xor_sync(0xffffffffu, mx0, 1));
        mx0 = fmaxf(mx0, __shfl_xor_sync(0xffffffffu, mx0, 2));
        mx1 = fmaxf(mx1, __shfl_xor_sync(0xffffffffu, mx1, 1));
        mx1 = fmaxf(mx1, __shfl_xor_sync(0xffffffffu, mx1, 2));
        float nm0 = fmaxf(m0, mx0), nm1 = fmaxf(m1, mx1);
        float c0 = __expf(m0 - nm0), c1 = __expf(m1 - nm1);
        m0 = nm0; m1 = nm1;

        float rs0 = 0.f, rs1 = 0.f;
        uint32_t aPh[4][4], aPl[4][4];
#pragma unroll
        for (int nt = 0; nt < 8; nt++) {
            float p0 = __expf(S[nt][0] - nm0);
            float p1 = __expf(S[nt][1] - nm0);
            float p2 = __expf(S[nt][2] - nm1);
            float p3 = __expf(S[nt][3] - nm1);
            rs0 += p0 + p1;
            rs1 += p2 + p3;
            uint32_t h01 = packbf(p0, p1), h23 = packbf(p2, p3);
            uint32_t l01 = packbf(p0 - __uint_as_float(h01 << 16),
                                  p1 - __uint_as_float(h01 & 0xFFFF0000u));
            uint32_t l23 = packbf(p2 - __uint_as_float(h23 << 16),
                                  p3 - __uint_as_float(h23 & 0xFFFF0000u));
            int ks = nt >> 1, hf = (nt & 1) * 2;
            aPh[ks][hf] = h01; aPh[ks][hf + 1] = h23;
            aPl[ks][hf] = l01; aPl[ks][hf + 1] = l23;
        }
        rs0 += __shfl_xor_sync(0xffffffffu, rs0, 1);
        rs0 += __shfl_xor_sync(0xffffffffu, rs0, 2);
        rs1 += __shfl_xor_sync(0xffffffffu, rs1, 1);
        rs1 += __shfl_xor_sync(0xffffffffu, rs1, 2);
        l0 = l0 * c0 + rs0;
        l1 = l1 * c1 + rs1;
#pragma unroll
        for (int nt = 0; nt < 8; nt++) {
            O[nt][0] *= c0; O[nt][1] *= c0;
            O[nt][2] *= c1; O[nt][3] *= c1;
        }

        // pending: V(t), K(t+1), V(t+1). Wait V(t).
        CP_WAITG(2);
        __syncthreads();

        // ---- O += P V (3-pass split), V frags via ldmatrix.trans
#pragma unroll
        for (int ks = 0; ks < 4; ks++) {
            uint32_t vf[8][2];
            int kvrow = ks * 16 + (lane & 15);
            uint32_t rsw = kvrow * 128;
#pragma unroll
            for (int p = 0; p < 4; p++) {
                int dseg = 2 * p + (lane >> 4);
                uint32_t addr = stg + 16384 + rsw + ((dseg ^ (kvrow & 7)) << 4);
                ldsm4t(&vf[2 * p][0], addr);
            }
#pragma unroll
            for (int nt = 0; nt < 8; nt++) {
                mma16816(O[nt], aPh[ks], vf[nt]);
                mma16816(O[nt], aPl[ks], vf[nt]);
            }
#pragma unroll
            for (int p = 0; p < 4; p++) {
                int dseg = 2 * p + (lane >> 4);
                uint32_t addr = stg + 24576 + rsw + ((dseg ^ (kvrow & 7)) << 4);
                ldsm4t(&vf[2 * p][0], addr);
            }
#pragma unroll
            for (int nt = 0; nt < 8; nt++)
                mma16816(O[nt], aPh[ks], vf[nt]);
        }
    }

    // ---- normalize + write out[b][l][h*64+d]
    float i0 = 1.f / l0, i1 = 1.f / l1;
    size_t r0 = (size_t)(b * LL + qb + wm + gid);
#pragma unroll
    for (int nt = 0; nt < 8; nt++) {
        int d = h * HDIM + nt * 8 + 2 * tg;
        *(float2*)(out + r0 * DD + d) = make_float2(O[nt][0] * i0, O[nt][1] * i0);
        *(float2*)(out + (r0 + 8) * DD + d) = make_float2(O[nt][2] * i1, O[nt][3] * i1);
    }
}

// ---------------------------------------------------------------------------
extern "C" void kernel_launch(void* const* d_in, const int* in_sizes, int n_in,
                              void* d_out, int out_size)
{
    const float* x    = (const float*)d_in[0];
    const float* w_in = (const float*)d_in[1];
    const float* off  = (const float*)d_in[2];
    const float* amp  = (const float*)d_in[3];
    const float* shp  = (const float*)d_in[4];
    float* out = (float*)d_out;

    scores_kernel<<<dim3(HH, 8), 256>>>(off, amp, shp);

    {
        __nv_bfloat16* abig;
        __nv_bfloat16* bbig;
        cudaGetSymbolAddress((void**)&abig, g_Abig);
        cudaGetSymbolAddress((void**)&bbig, g_Bbig);
        convert_kernel<<<(MTOT * DD / 4) / 256, 256>>>(x, abig);
        convert_kernel<<<(D3 * DD / 4) / 256, 256>>>(w_in, bbig);
    }

    {
        const int smem_bytes = 3 * STG_BYTES;  // 98304
        cudaFuncSetAttribute(proj_mma, cudaFuncAttributeMaxDynamicSharedMemorySize,
                             smem_bytes);
        dim3 grid(D3 / 128, MTOT / 128);
        proj_mma<<<grid, 256, smem_bytes>>>();
    }

    {
        const int smem_bytes = 98304 + 2 * 192 * 4;  // 99840
        cudaFuncSetAttribute(attn_mma, cudaFuncAttributeMaxDynamicSharedMemorySize,
                             smem_bytes);
        dim3 agrid(LL / 128, HH, BB);
        attn_mma<<<agrid, 256, smem_bytes>>>(out);
    }
}